// round 6
// baseline (speedup 1.0000x reference)
#include <cuda_runtime.h>
#include <cuda_bf16.h>
#include <math.h>
#include <stdint.h>

#define EPS 1e-6f
#define MAXB 1024
#define MAXN 40000
#define MAXD 512

// ===================== fast math =====================
__device__ __forceinline__ float fast_lg2(float x) {
    float r; asm("lg2.approx.f32 %0, %1;" : "=f"(r) : "f"(x)); return r;
}
__device__ __forceinline__ float fast_ex2(float x) {
    float r; asm("ex2.approx.f32 %0, %1;" : "=f"(r) : "f"(x)); return r;
}
__device__ __forceinline__ uint32_t smem_u32(const void* p) {
    uint32_t a;
    asm("{ .reg .u64 t; cvta.to.shared.u64 t, %1; cvt.u32.u64 %0, t; }" : "=r"(a) : "l"(p));
    return a;
}

// ===================== mma.sync helpers (arch-generic tensor path) =====================
#define LDSM_X4(r0, r1, r2, r3, addr)                                          \
    asm volatile("ldmatrix.sync.aligned.m8n8.x4.shared.b16 {%0,%1,%2,%3}, [%4];" \
        : "=r"(r0), "=r"(r1), "=r"(r2), "=r"(r3) : "r"(addr))

#define MMA16816(c, a, b0, b1)                                                 \
    asm volatile("mma.sync.aligned.m16n8k16.row.col.f32.bf16.bf16.f32 "        \
        "{%0,%1,%2,%3}, {%4,%5,%6,%7}, {%8,%9}, {%0,%1,%2,%3};"                \
        : "+f"((c)[0]), "+f"((c)[1]), "+f"((c)[2]), "+f"((c)[3])               \
        : "r"((a)[0]), "r"((a)[1]), "r"((a)[2]), "r"((a)[3]), "r"(b0), "r"(b1))

__device__ __forceinline__ void cp16(uint32_t dst, const void* src, bool pred) {
    int sz = pred ? 16 : 0;   // src-size 0 => 16B zero-fill (keeps OOB tiles clean)
    asm volatile("cp.async.cg.shared.global [%0], [%1], 16, %2;"
        :: "r"(dst), "l"(src), "r"(sz) : "memory");
}
#define CP_COMMIT() asm volatile("cp.async.commit_group;" ::: "memory")
#define CP_WAIT(n)  asm volatile("cp.async.wait_group %0;" :: "n"(n) : "memory")

// ===================== scratch (__device__ globals; no allocs) =====================
__device__ __align__(16) __nv_bfloat16 g_Qb[MAXB * MAXD];
__device__ __align__(16) __nv_bfloat16 g_Cb[MAXN * MAXD];
__device__ float g_ysq[MAXN];
__device__ float g_eb[MAXN];
__device__ float g_rowc[MAXB * 8];
__device__ float g_sumexp[MAXB];

// ===================== init =====================
__global__ void hy_init(float* out, int B) {
    int i = blockIdx.x * blockDim.x + threadIdx.x;
    if (i < B) g_sumexp[i] = 0.f;
    if (i == 0) out[0] = 0.f;
}

// ===================== prep candidates =====================
__global__ void hy_prep_y(const float* __restrict__ C,
                          const float* __restrict__ bias, int N, int d) {
    int w = (blockIdx.x * blockDim.x + threadIdx.x) >> 5;
    int lane = threadIdx.x & 31;
    if (w >= N) return;
    const float* row = C + (long)w * d;
    __nv_bfloat16* brow = g_Cb + (long)w * d;
    float s = 0.f;
    for (int k = lane * 4; k < d; k += 128) {
        float4 v = *reinterpret_cast<const float4*>(row + k);
        s += v.x*v.x + v.y*v.y + v.z*v.z + v.w*v.w;
        __nv_bfloat162* bp = reinterpret_cast<__nv_bfloat162*>(brow + k);
        bp[0] = __floats2bfloat162_rn(v.x, v.y);
        bp[1] = __floats2bfloat162_rn(v.z, v.w);
    }
    #pragma unroll
    for (int o = 16; o > 0; o >>= 1) s += __shfl_xor_sync(0xffffffffu, s, o);
    if (lane == 0) { g_ysq[w] = s; g_eb[w] = expf(bias[w]); }
}

// ===================== prep queries =====================
__global__ void hy_prep_x(const float* __restrict__ Q,
                          const float* __restrict__ curv, int B, int d) {
    int w = (blockIdx.x * blockDim.x + threadIdx.x) >> 5;
    int lane = threadIdx.x & 31;
    if (w >= B) return;
    const float* row = Q + (long)w * d;
    __nv_bfloat16* brow = g_Qb + (long)w * d;
    float s = 0.f;
    for (int k = lane * 4; k < d; k += 128) {
        float4 v = *reinterpret_cast<const float4*>(row + k);
        s += v.x*v.x + v.y*v.y + v.z*v.z + v.w*v.w;
        __nv_bfloat162* bp = reinterpret_cast<__nv_bfloat162*>(brow + k);
        bp[0] = __floats2bfloat162_rn(v.x, v.y);
        bp[1] = __floats2bfloat162_rn(v.z, v.w);
    }
    #pragma unroll
    for (int o = 16; o > 0; o >>= 1) s += __shfl_xor_sync(0xffffffffu, s, o);
    if (lane == 0) {
        float c  = curv[w];
        float xs = s;
        float sc = sqrtf(c + EPS);
        float Bq = 1.f - c * xs;
        float* rc = g_rowc + w * 8;
        rc[0] = c;  rc[1] = xs;  rc[2] = Bq;  rc[3] = Bq * Bq;
        rc[4] = c * c * xs;  rc[5] = sc;
        rc[6] = -1.f / (sc + EPS);
        rc[7] = 1.f / (sc + EPS) - EPS;
    }
}

// ===================== main HMMA fused kernel (4-stage pipeline) =====================
#define BM 128
#define BN 128
#define BK 32
#define RSB 80               // padded row stride in bytes (40 bf16)
#define HTILE (BM * RSB)     // 10240 bytes (A or B half of a stage)
#define STAGE_B (2 * HTILE)  // 20480 bytes per stage
#define STAGES 4
#define RC_OFF  (STAGES * STAGE_B)            // 81920
#define YSQ_OFF (RC_OFF + BM * 8 * 4)         // 86016
#define EB_OFF  (YSQ_OFF + BN * 4)            // 86528
#define SMEM_TOT (EB_OFF + BN * 4)            // 87040

__global__ __launch_bounds__(256, 2)
void hy_mma(int B, int N, int d) {
    extern __shared__ __align__(16) char smem[];
    const uint32_t sb = smem_u32(smem);

    const int tid = threadIdx.x;
    const int wid = tid >> 5;
    const int lane = tid & 31;
    const int m0 = blockIdx.y * BM;
    const int n0 = blockIdx.x * BN;
    const int NKT = d / BK;

    float* rc_s  = reinterpret_cast<float*>(smem + RC_OFF);
    float* ysq_s = reinterpret_cast<float*>(smem + YSQ_OFF);
    float* eb_s  = reinterpret_cast<float*>(smem + EB_OFF);

    // stage epilogue constants
    for (int idx = tid; idx < BM * 8; idx += 256) {
        int r = idx >> 3, cc = idx & 7, gm = m0 + r;
        rc_s[idx] = (gm < B) ? g_rowc[gm * 8 + cc] : 0.f;
    }
    for (int idx = tid; idx < BN; idx += 256) {
        int gn = n0 + idx;
        ysq_s[idx] = (gn < N) ? g_ysq[gn] : 0.f;
        eb_s[idx]  = (gn < N) ? g_eb[gn]  : 0.f;
    }

    // ---- loader geometry (hoisted; row fixed per thread) ----
    const int lrow = tid >> 2;          // 0..63 (+64 for second chunk)
    const int lc16 = tid & 3;           // 16B column within 64B row
    const __nv_bfloat16* srcA[2];
    const __nv_bfloat16* srcB[2];
    bool okA[2], okB[2];
    uint32_t dstA[2], dstB[2];          // stage-0 addresses; add s*STAGE_B
    #pragma unroll
    for (int i = 0; i < 2; i++) {
        int row = lrow + i * 64;
        int gm = m0 + row;  okA[i] = gm < B;
        int gn = n0 + row;  okB[i] = gn < N;
        srcA[i] = g_Qb + (long)(okA[i] ? gm : 0) * d + lc16 * 8;
        srcB[i] = g_Cb + (long)(okB[i] ? gn : 0) * d + lc16 * 8;
        dstA[i] = sb + row * RSB + lc16 * 16;
        dstB[i] = sb + HTILE + row * RSB + lc16 * 16;
    }

    // prologue: prefetch stages 0..2
    #pragma unroll
    for (int s = 0; s < STAGES - 1; s++) {
        uint32_t so = s * STAGE_B;
        #pragma unroll
        for (int i = 0; i < 2; i++) cp16(dstA[i] + so, srcA[i] + s * BK, okA[i]);
        #pragma unroll
        for (int i = 0; i < 2; i++) cp16(dstB[i] + so, srcB[i] + s * BK, okB[i]);
        CP_COMMIT();
    }

    // ---- warp tile: 32(m) x 64(n) ----
    const int wm = (wid & 3) * 32;
    const int wn = (wid >> 2) * 64;
    const uint32_t a_base = sb + (wm + (lane & 15)) * RSB + (lane >> 4) * 16;
    const uint32_t b_base = sb + HTILE + (wn + (lane >> 4) * 8 + (lane & 7)) * RSB
                               + ((lane >> 3) & 1) * 16;

    float acc[2][8][4];
    #pragma unroll
    for (int mi = 0; mi < 2; mi++)
        #pragma unroll
        for (int ni = 0; ni < 8; ni++)
            #pragma unroll
            for (int q = 0; q < 4; q++) acc[mi][ni][q] = 0.f;

    for (int kt = 0; kt < NKT; kt++) {
        CP_WAIT(STAGES - 2);
        __syncthreads();

        // prefetch stage kt+3 into buffer (kt+3)%4  (== (kt-1)%4, safe after sync)
        if (kt + STAGES - 1 < NKT) {
            const int kf = kt + STAGES - 1;
            const uint32_t so = (kf & (STAGES - 1)) * STAGE_B;
            #pragma unroll
            for (int i = 0; i < 2; i++) cp16(dstA[i] + so, srcA[i] + kf * BK, okA[i]);
            #pragma unroll
            for (int i = 0; i < 2; i++) cp16(dstB[i] + so, srcB[i] + kf * BK, okB[i]);
        }
        CP_COMMIT();

        const uint32_t so = (kt & (STAGES - 1)) * STAGE_B;
        #pragma unroll
        for (int ks = 0; ks < 2; ks++) {
            uint32_t a[2][4];
            #pragma unroll
            for (int mi = 0; mi < 2; mi++)
                LDSM_X4(a[mi][0], a[mi][1], a[mi][2], a[mi][3],
                        a_base + so + mi * 16 * RSB + ks * 32);
            uint32_t b[4][4];
            #pragma unroll
            for (int g = 0; g < 4; g++)
                LDSM_X4(b[g][0], b[g][1], b[g][2], b[g][3],
                        b_base + so + g * 16 * RSB + ks * 32);
            #pragma unroll
            for (int mi = 0; mi < 2; mi++)
                #pragma unroll
                for (int ni = 0; ni < 8; ni++)
                    MMA16816(acc[mi][ni], a[mi], b[ni >> 1][(ni & 1) * 2],
                             b[ni >> 1][(ni & 1) * 2 + 1]);
        }
    }

    // ---------------- epilogue ----------------
    #pragma unroll
    for (int mi = 0; mi < 2; mi++) {
        #pragma unroll
        for (int half = 0; half < 2; half++) {
            const int mrow = wm + mi * 16 + half * 8 + (lane >> 2);
            const int gm = m0 + mrow;
            const float* rc = rc_s + mrow * 8;
            const float c    = rc[0];
            const float xs   = rc[1];
            const float Bq   = rc[2];
            const float Bq2  = rc[3];
            const float c2xs = rc[4];
            const float sc   = rc[5];
            const float p    = rc[6];
            const float maxn = rc[7];
            const float m2c  = -2.f * c;
            const float m2Bq = -2.f * Bq;

            float rowsum = 0.f;
            #pragma unroll
            for (int ni = 0; ni < 8; ni++) {
                #pragma unroll
                for (int q = 0; q < 2; q++) {
                    float u  = acc[mi][ni][half * 2 + q];
                    int col  = wn + ni * 8 + 2 * (lane & 3) + q;
                    float v  = ysq_s[col];
                    float eb = eb_s[col];
                    float t    = fmaf(-2.f, u, v);
                    float A    = fmaf(c, t, 1.f);
                    float denp = fmaf(c2xs, v, fmaf(m2c, u, 1.f)) + EPS;
                    float ns   = fmaf(Bq2, v, A * fmaf(m2Bq, u, A * xs));
                    float r0   = sqrtf(fmaxf(ns, 0.f));
                    r0 = fminf(fmaxf(r0, EPS * denp), maxn * denp);
                    float s    = sc * r0;
                    float ratio = __fdividef(denp + s, denp - s);   // (1+z)/(1-z)
                    rowsum = fmaf(eb, fast_ex2(p * fast_lg2(ratio)), rowsum);
                }
            }
            rowsum += __shfl_xor_sync(0xffffffffu, rowsum, 1);
            rowsum += __shfl_xor_sync(0xffffffffu, rowsum, 2);
            if ((lane & 3) == 0 && gm < B) atomicAdd(&g_sumexp[gm], rowsum);
        }
    }
}

// ===================== finalize =====================
__global__ void hy_finalize(const float* __restrict__ Q, const float* __restrict__ C,
                            const float* __restrict__ bias, const int* __restrict__ tgt,
                            float* out, int B, int N, int d) {
    int w = (blockIdx.x * blockDim.x + threadIdx.x) >> 5;
    int lane = threadIdx.x & 31;
    if (w >= B) return;
    int t = tgt[w];
    const float* q  = Q + (long)w * d;
    const float* cd = C + (long)t * d;
    float s = 0.f;
    for (int k = lane * 4; k < d; k += 128) {
        float4 a = *reinterpret_cast<const float4*>(q + k);
        float4 b = *reinterpret_cast<const float4*>(cd + k);
        s += a.x*b.x + a.y*b.y + a.z*b.z + a.w*b.w;
    }
    #pragma unroll
    for (int o = 16; o > 0; o >>= 1) s += __shfl_xor_sync(0xffffffffu, s, o);
    if (lane == 0) {
        const float* rc = g_rowc + w * 8;
        float c = rc[0], xs = rc[1], Bq = rc[2], Bq2 = rc[3], c2xs = rc[4];
        float sc = rc[5], maxn = rc[7];
        float u = s, v = g_ysq[t];
        float tt  = fmaf(-2.f, u, v);
        float A   = fmaf(c, tt, 1.f);
        float den = fmaf(c2xs, v, fmaf(-2.f * c, u, 1.f));
        float ns  = fmaf(Bq2, v, A * fmaf(-2.f * Bq, u, A * xs));
        float r   = sqrtf(fmaxf(ns, 0.f));
        float dn  = r / (den + EPS);
        dn = fminf(fmaxf(dn, EPS), maxn);
        float z = fminf(sc * dn, 1.f - EPS);
        float dist = (2.f / (sc + EPS)) * atanhf(z);
        float tlogit = bias[t] - dist;
        float lse = logf(g_sumexp[w]);
        atomicAdd(out, (lse - tlogit) * (1.f / (float)B));
    }
}

// ===================== launch =====================
extern "C" void kernel_launch(void* const* d_in, const int* in_sizes, int n_in,
                              void* d_out, int out_size) {
    const float* Q    = (const float*)d_in[0];
    const float* C    = (const float*)d_in[1];
    const float* bias = (const float*)d_in[2];
    const float* curv = (const float*)d_in[3];
    const int*   tgt  = (const int*)d_in[4];
    float* out = (float*)d_out;

    int B = in_sizes[3];
    int N = in_sizes[2];
    int d = in_sizes[0] / B;

    hy_init<<<(B + 255) / 256, 256>>>(out, B);
    hy_prep_y<<<(N * 32 + 255) / 256, 256>>>(C, bias, N, d);
    hy_prep_x<<<(B * 32 + 255) / 256, 256>>>(Q, curv, B, d);

    static bool attr_done = false;
    if (!attr_done) {
        cudaFuncSetAttribute(hy_mma, cudaFuncAttributeMaxDynamicSharedMemorySize, SMEM_TOT);
        attr_done = true;
    }
    dim3 grid((N + BN - 1) / BN, (B + BM - 1) / BM);
    hy_mma<<<grid, 256, SMEM_TOT>>>(B, N, d);

    hy_finalize<<<(B * 32 + 255) / 256, 256>>>(Q, C, bias, tgt, out, B, N, d);
}

// round 7
// speedup vs baseline: 1.2295x; 1.2295x over previous
#include <cuda_runtime.h>
#include <cuda_bf16.h>
#include <math.h>
#include <stdint.h>

#define EPS 1e-6f
#define MAXB 1024
#define MAXN 40000
#define MAXD 512

// ===================== fast math =====================
__device__ __forceinline__ float fast_lg2(float x) {
    float r; asm("lg2.approx.f32 %0, %1;" : "=f"(r) : "f"(x)); return r;
}
__device__ __forceinline__ float fast_ex2(float x) {
    float r; asm("ex2.approx.f32 %0, %1;" : "=f"(r) : "f"(x)); return r;
}
__device__ __forceinline__ uint32_t smem_u32(const void* p) {
    uint32_t a;
    asm("{ .reg .u64 t; cvta.to.shared.u64 t, %1; cvt.u32.u64 %0, t; }" : "=r"(a) : "l"(p));
    return a;
}

// ===================== mma.sync helpers (arch-generic tensor path) =====================
#define LDSM_X4(r0, r1, r2, r3, addr)                                          \
    asm volatile("ldmatrix.sync.aligned.m8n8.x4.shared.b16 {%0,%1,%2,%3}, [%4];" \
        : "=r"(r0), "=r"(r1), "=r"(r2), "=r"(r3) : "r"(addr))

#define MMA16816(c, a, b0, b1)                                                 \
    asm volatile("mma.sync.aligned.m16n8k16.row.col.f32.bf16.bf16.f32 "        \
        "{%0,%1,%2,%3}, {%4,%5,%6,%7}, {%8,%9}, {%0,%1,%2,%3};"                \
        : "+f"((c)[0]), "+f"((c)[1]), "+f"((c)[2]), "+f"((c)[3])               \
        : "r"((a)[0]), "r"((a)[1]), "r"((a)[2]), "r"((a)[3]), "r"(b0), "r"(b1))

__device__ __forceinline__ void cp16(uint32_t dst, const void* src, bool pred) {
    int sz = pred ? 16 : 0;   // src-size 0 => 16B zero-fill (keeps OOB tiles clean)
    asm volatile("cp.async.cg.shared.global [%0], [%1], 16, %2;"
        :: "r"(dst), "l"(src), "r"(sz) : "memory");
}
#define CP_COMMIT() asm volatile("cp.async.commit_group;" ::: "memory")
#define CP_WAIT(n)  asm volatile("cp.async.wait_group %0;" :: "n"(n) : "memory")

// ===================== scratch (__device__ globals; no allocs) =====================
__device__ __align__(16) __nv_bfloat16 g_Qb[MAXB * MAXD];
__device__ __align__(16) __nv_bfloat16 g_Cb[MAXN * MAXD];
__device__ float g_ysq[MAXN];
__device__ float g_eb[MAXN];
__device__ float g_rowc[MAXB * 8];
__device__ float g_sumexp[MAXB];

// ===================== init =====================
__global__ void hy_init(float* out, int B) {
    int i = blockIdx.x * blockDim.x + threadIdx.x;
    if (i < B) g_sumexp[i] = 0.f;
    if (i == 0) out[0] = 0.f;
}

// ===================== prep candidates =====================
__global__ void hy_prep_y(const float* __restrict__ C,
                          const float* __restrict__ bias, int N, int d) {
    int w = (blockIdx.x * blockDim.x + threadIdx.x) >> 5;
    int lane = threadIdx.x & 31;
    if (w >= N) return;
    const float* row = C + (long)w * d;
    __nv_bfloat16* brow = g_Cb + (long)w * d;
    float s = 0.f;
    for (int k = lane * 4; k < d; k += 128) {
        float4 v = *reinterpret_cast<const float4*>(row + k);
        s += v.x*v.x + v.y*v.y + v.z*v.z + v.w*v.w;
        __nv_bfloat162* bp = reinterpret_cast<__nv_bfloat162*>(brow + k);
        bp[0] = __floats2bfloat162_rn(v.x, v.y);
        bp[1] = __floats2bfloat162_rn(v.z, v.w);
    }
    #pragma unroll
    for (int o = 16; o > 0; o >>= 1) s += __shfl_xor_sync(0xffffffffu, s, o);
    if (lane == 0) { g_ysq[w] = s; g_eb[w] = expf(bias[w]); }
}

// ===================== prep queries =====================
__global__ void hy_prep_x(const float* __restrict__ Q,
                          const float* __restrict__ curv, int B, int d) {
    int w = (blockIdx.x * blockDim.x + threadIdx.x) >> 5;
    int lane = threadIdx.x & 31;
    if (w >= B) return;
    const float* row = Q + (long)w * d;
    __nv_bfloat16* brow = g_Qb + (long)w * d;
    float s = 0.f;
    for (int k = lane * 4; k < d; k += 128) {
        float4 v = *reinterpret_cast<const float4*>(row + k);
        s += v.x*v.x + v.y*v.y + v.z*v.z + v.w*v.w;
        __nv_bfloat162* bp = reinterpret_cast<__nv_bfloat162*>(brow + k);
        bp[0] = __floats2bfloat162_rn(v.x, v.y);
        bp[1] = __floats2bfloat162_rn(v.z, v.w);
    }
    #pragma unroll
    for (int o = 16; o > 0; o >>= 1) s += __shfl_xor_sync(0xffffffffu, s, o);
    if (lane == 0) {
        float c  = curv[w];
        float xs = s;
        float sc = sqrtf(c + EPS);
        float Bq = 1.f - c * xs;
        float* rc = g_rowc + w * 8;
        rc[0] = c;  rc[1] = xs;  rc[2] = Bq;  rc[3] = Bq * Bq;
        rc[4] = c * c * xs;  rc[5] = sc;
        rc[6] = -1.f / (sc + EPS);
        rc[7] = 1.f / (sc + EPS) - EPS;
    }
}

// ===================== main HMMA fused kernel (BK=64, 2-stage) =====================
#define BM 128
#define BN 128
#define BK 64
#define RSB 144                 // padded row stride bytes (64 bf16 = 128B + 16 pad)
#define HTILE (BM * RSB)        // 18432 bytes
#define STAGE_B (2 * HTILE)     // 36864 bytes per stage (A + B)
#define RC_OFF  (2 * STAGE_B)              // 73728
#define YSQ_OFF (RC_OFF + BM * 8 * 4)      // 77824
#define EB_OFF  (YSQ_OFF + BN * 4)         // 78336
#define SMEM_TOT (EB_OFF + BN * 4)         // 78848

__global__ __launch_bounds__(256)
void hy_mma(int B, int N, int d) {
    extern __shared__ __align__(16) char smem[];
    const uint32_t sb = smem_u32(smem);

    const int tid = threadIdx.x;
    const int wid = tid >> 5;
    const int lane = tid & 31;
    const int m0 = blockIdx.y * BM;
    const int n0 = blockIdx.x * BN;
    const int NKT = d / BK;

    float* rc_s  = reinterpret_cast<float*>(smem + RC_OFF);
    float* ysq_s = reinterpret_cast<float*>(smem + YSQ_OFF);
    float* eb_s  = reinterpret_cast<float*>(smem + EB_OFF);

    // stage epilogue constants
    for (int idx = tid; idx < BM * 8; idx += 256) {
        int r = idx >> 3, cc = idx & 7, gm = m0 + r;
        rc_s[idx] = (gm < B) ? g_rowc[gm * 8 + cc] : 0.f;
    }
    for (int idx = tid; idx < BN; idx += 256) {
        int gn = n0 + idx;
        ysq_s[idx] = (gn < N) ? g_ysq[gn] : 0.f;
        eb_s[idx]  = (gn < N) ? g_eb[gn]  : 0.f;
    }

    // loader geometry: each thread owns one (row, half-row) of A and of B
    const int lrow  = tid >> 1;          // 0..127
    const int lhalf = tid & 1;           // 32-elem half of the 64-elem k-chunk
    const int gmL = m0 + lrow;  const bool okA = gmL < B;
    const int gnL = n0 + lrow;  const bool okB = gnL < N;

    // ---- prefetch k-chunk 0 into stage 0 ----
    {
        const __nv_bfloat16* sa = g_Qb + (long)(okA ? gmL : 0) * d + lhalf * 32;
        const __nv_bfloat16* sc_ = g_Cb + (long)(okB ? gnL : 0) * d + lhalf * 32;
        uint32_t da = sb + lrow * RSB + lhalf * 64;
        uint32_t db = sb + HTILE + lrow * RSB + lhalf * 64;
        #pragma unroll
        for (int j = 0; j < 4; j++) cp16(da + j * 16, sa + j * 8, okA);
        #pragma unroll
        for (int j = 0; j < 4; j++) cp16(db + j * 16, sc_ + j * 8, okB);
        CP_COMMIT();
    }

    // ---- warp tile: 32(m) x 64(n) ----
    const int wm = (wid & 3) * 32;
    const int wn = (wid >> 2) * 64;
    const uint32_t a_base = sb + (wm + (lane & 15)) * RSB + (lane >> 4) * 16;
    const uint32_t b_base = sb + HTILE + (wn + (lane >> 4) * 8 + (lane & 7)) * RSB
                               + ((lane >> 3) & 1) * 16;

    float acc[2][8][4];
    #pragma unroll
    for (int mi = 0; mi < 2; mi++)
        #pragma unroll
        for (int ni = 0; ni < 8; ni++)
            #pragma unroll
            for (int q = 0; q < 4; q++) acc[mi][ni][q] = 0.f;

    for (int kt = 0; kt < NKT; kt++) {
        // prefetch next stage, then wait for current
        if (kt + 1 < NKT) {
            const uint32_t so = ((kt + 1) & 1) * STAGE_B;
            const __nv_bfloat16* sa = g_Qb + (long)(okA ? gmL : 0) * d + (kt + 1) * BK + lhalf * 32;
            const __nv_bfloat16* sc_ = g_Cb + (long)(okB ? gnL : 0) * d + (kt + 1) * BK + lhalf * 32;
            uint32_t da = sb + so + lrow * RSB + lhalf * 64;
            uint32_t db = sb + so + HTILE + lrow * RSB + lhalf * 64;
            #pragma unroll
            for (int j = 0; j < 4; j++) cp16(da + j * 16, sa + j * 8, okA);
            #pragma unroll
            for (int j = 0; j < 4; j++) cp16(db + j * 16, sc_ + j * 8, okB);
            CP_COMMIT();
            CP_WAIT(1);
        } else {
            CP_WAIT(0);
        }
        __syncthreads();

        const uint32_t so = (kt & 1) * STAGE_B;
        #pragma unroll
        for (int ks = 0; ks < 4; ks++) {          // 4 x k16 per stage, one basic block
            uint32_t a[2][4];
            #pragma unroll
            for (int mi = 0; mi < 2; mi++)
                LDSM_X4(a[mi][0], a[mi][1], a[mi][2], a[mi][3],
                        a_base + so + mi * 16 * RSB + ks * 32);
            uint32_t b[4][4];
            #pragma unroll
            for (int g = 0; g < 4; g++)
                LDSM_X4(b[g][0], b[g][1], b[g][2], b[g][3],
                        b_base + so + g * 16 * RSB + ks * 32);
            #pragma unroll
            for (int mi = 0; mi < 2; mi++)
                #pragma unroll
                for (int ni = 0; ni < 8; ni++)
                    MMA16816(acc[mi][ni], a[mi], b[ni >> 1][(ni & 1) * 2],
                             b[ni >> 1][(ni & 1) * 2 + 1]);
        }
        __syncthreads();
    }

    // ---------------- epilogue ----------------
    #pragma unroll
    for (int mi = 0; mi < 2; mi++) {
        #pragma unroll
        for (int half = 0; half < 2; half++) {
            const int mrow = wm + mi * 16 + half * 8 + (lane >> 2);
            const int gm = m0 + mrow;
            const float* rc = rc_s + mrow * 8;
            const float c    = rc[0];
            const float xs   = rc[1];
            const float Bq   = rc[2];
            const float Bq2  = rc[3];
            const float c2xs = rc[4];
            const float sc   = rc[5];
            const float p    = rc[6];
            const float maxn = rc[7];
            const float m2c  = -2.f * c;
            const float m2Bq = -2.f * Bq;

            float rowsum = 0.f;
            #pragma unroll
            for (int ni = 0; ni < 8; ni++) {
                #pragma unroll
                for (int q = 0; q < 2; q++) {
                    float u  = acc[mi][ni][half * 2 + q];
                    int col  = wn + ni * 8 + 2 * (lane & 3) + q;
                    float v  = ysq_s[col];
                    float eb = eb_s[col];
                    float t    = fmaf(-2.f, u, v);
                    float A    = fmaf(c, t, 1.f);
                    float denp = fmaf(c2xs, v, fmaf(m2c, u, 1.f)) + EPS;
                    float ns   = fmaf(Bq2, v, A * fmaf(m2Bq, u, A * xs));
                    float r0   = sqrtf(fmaxf(ns, 0.f));
                    r0 = fminf(fmaxf(r0, EPS * denp), maxn * denp);
                    float s    = sc * r0;
                    float ratio = __fdividef(denp + s, denp - s);   // (1+z)/(1-z)
                    rowsum = fmaf(eb, fast_ex2(p * fast_lg2(ratio)), rowsum);
                }
            }
            rowsum += __shfl_xor_sync(0xffffffffu, rowsum, 1);
            rowsum += __shfl_xor_sync(0xffffffffu, rowsum, 2);
            if ((lane & 3) == 0 && gm < B) atomicAdd(&g_sumexp[gm], rowsum);
        }
    }
}

// ===================== finalize =====================
__global__ void hy_finalize(const float* __restrict__ Q, const float* __restrict__ C,
                            const float* __restrict__ bias, const int* __restrict__ tgt,
                            float* out, int B, int N, int d) {
    int w = (blockIdx.x * blockDim.x + threadIdx.x) >> 5;
    int lane = threadIdx.x & 31;
    if (w >= B) return;
    int t = tgt[w];
    const float* q  = Q + (long)w * d;
    const float* cd = C + (long)t * d;
    float s = 0.f;
    for (int k = lane * 4; k < d; k += 128) {
        float4 a = *reinterpret_cast<const float4*>(q + k);
        float4 b = *reinterpret_cast<const float4*>(cd + k);
        s += a.x*b.x + a.y*b.y + a.z*b.z + a.w*b.w;
    }
    #pragma unroll
    for (int o = 16; o > 0; o >>= 1) s += __shfl_xor_sync(0xffffffffu, s, o);
    if (lane == 0) {
        const float* rc = g_rowc + w * 8;
        float c = rc[0], xs = rc[1], Bq = rc[2], Bq2 = rc[3], c2xs = rc[4];
        float sc = rc[5], maxn = rc[7];
        float u = s, v = g_ysq[t];
        float tt  = fmaf(-2.f, u, v);
        float A   = fmaf(c, tt, 1.f);
        float den = fmaf(c2xs, v, fmaf(-2.f * c, u, 1.f));
        float ns  = fmaf(Bq2, v, A * fmaf(-2.f * Bq, u, A * xs));
        float r   = sqrtf(fmaxf(ns, 0.f));
        float dn  = r / (den + EPS);
        dn = fminf(fmaxf(dn, EPS), maxn);
        float z = fminf(sc * dn, 1.f - EPS);
        float dist = (2.f / (sc + EPS)) * atanhf(z);
        float tlogit = bias[t] - dist;
        float lse = logf(g_sumexp[w]);
        atomicAdd(out, (lse - tlogit) * (1.f / (float)B));
    }
}

// ===================== launch =====================
extern "C" void kernel_launch(void* const* d_in, const int* in_sizes, int n_in,
                              void* d_out, int out_size) {
    const float* Q    = (const float*)d_in[0];
    const float* C    = (const float*)d_in[1];
    const float* bias = (const float*)d_in[2];
    const float* curv = (const float*)d_in[3];
    const int*   tgt  = (const int*)d_in[4];
    float* out = (float*)d_out;

    int B = in_sizes[3];
    int N = in_sizes[2];
    int d = in_sizes[0] / B;

    hy_init<<<(B + 255) / 256, 256>>>(out, B);
    hy_prep_y<<<(N * 32 + 255) / 256, 256>>>(C, bias, N, d);
    hy_prep_x<<<(B * 32 + 255) / 256, 256>>>(Q, curv, B, d);

    cudaFuncSetAttribute(hy_mma, cudaFuncAttributeMaxDynamicSharedMemorySize, SMEM_TOT);
    dim3 grid((N + BN - 1) / BN, (B + BM - 1) / BM);
    hy_mma<<<grid, 256, SMEM_TOT>>>(B, N, d);

    hy_finalize<<<(B * 32 + 255) / 256, 256>>>(Q, C, bias, tgt, out, B, N, d);
}

// round 8
// speedup vs baseline: 1.3948x; 1.1345x over previous
#include <cuda_runtime.h>
#include <cuda_bf16.h>
#include <math.h>
#include <stdint.h>

#define EPS 1e-6f
#define MAXB 1024
#define MAXN 40000
#define MAXD 512

// ===================== fast math =====================
__device__ __forceinline__ float fast_lg2(float x) {
    float r; asm("lg2.approx.f32 %0, %1;" : "=f"(r) : "f"(x)); return r;
}
__device__ __forceinline__ float fast_ex2(float x) {
    float r; asm("ex2.approx.f32 %0, %1;" : "=f"(r) : "f"(x)); return r;
}
__device__ __forceinline__ uint32_t smem_u32(const void* p) {
    uint32_t a;
    asm("{ .reg .u64 t; cvta.to.shared.u64 t, %1; cvt.u32.u64 %0, t; }" : "=r"(a) : "l"(p));
    return a;
}

// ===================== mma.sync helpers =====================
#define LDSM_X4(r0, r1, r2, r3, addr)                                          \
    asm volatile("ldmatrix.sync.aligned.m8n8.x4.shared.b16 {%0,%1,%2,%3}, [%4];" \
        : "=r"(r0), "=r"(r1), "=r"(r2), "=r"(r3) : "r"(addr))

#define MMA16816(c, a, b0, b1)                                                 \
    asm volatile("mma.sync.aligned.m16n8k16.row.col.f32.bf16.bf16.f32 "        \
        "{%0,%1,%2,%3}, {%4,%5,%6,%7}, {%8,%9}, {%0,%1,%2,%3};"                \
        : "+f"((c)[0]), "+f"((c)[1]), "+f"((c)[2]), "+f"((c)[3])               \
        : "r"((a)[0]), "r"((a)[1]), "r"((a)[2]), "r"((a)[3]), "r"(b0), "r"(b1))

__device__ __forceinline__ void cp16(uint32_t dst, const void* src, bool pred) {
    int sz = pred ? 16 : 0;   // src-size 0 => zero-fill (keeps OOB tiles clean)
    asm volatile("cp.async.cg.shared.global [%0], [%1], 16, %2;"
        :: "r"(dst), "l"(src), "r"(sz) : "memory");
}
#define CP_COMMIT() asm volatile("cp.async.commit_group;" ::: "memory")
#define CP_WAIT(n)  asm volatile("cp.async.wait_group %0;" :: "n"(n) : "memory")

// ===================== scratch =====================
__device__ __align__(16) __nv_bfloat16 g_Qb[MAXB * MAXD];
__device__ __align__(16) __nv_bfloat16 g_Cb[MAXN * MAXD];
__device__ float g_ysq[MAXN];
__device__ float g_eb[MAXN];
__device__ float g_rowc[MAXB * 8];
__device__ float g_sumexp[MAXB];

// ===================== init =====================
__global__ void hy_init(float* out, int B) {
    int i = blockIdx.x * blockDim.x + threadIdx.x;
    if (i < B) g_sumexp[i] = 0.f;
    if (i == 0) out[0] = 0.f;
}

// ===================== prep candidates =====================
__global__ void hy_prep_y(const float* __restrict__ C,
                          const float* __restrict__ bias, int N, int d) {
    int w = (blockIdx.x * blockDim.x + threadIdx.x) >> 5;
    int lane = threadIdx.x & 31;
    if (w >= N) return;
    const float* row = C + (long)w * d;
    __nv_bfloat16* brow = g_Cb + (long)w * d;
    float s = 0.f;
    for (int k = lane * 4; k < d; k += 128) {
        float4 v = *reinterpret_cast<const float4*>(row + k);
        s += v.x*v.x + v.y*v.y + v.z*v.z + v.w*v.w;
        __nv_bfloat162* bp = reinterpret_cast<__nv_bfloat162*>(brow + k);
        bp[0] = __floats2bfloat162_rn(v.x, v.y);
        bp[1] = __floats2bfloat162_rn(v.z, v.w);
    }
    #pragma unroll
    for (int o = 16; o > 0; o >>= 1) s += __shfl_xor_sync(0xffffffffu, s, o);
    if (lane == 0) { g_ysq[w] = s; g_eb[w] = expf(bias[w]); }
}

// ===================== prep queries =====================
__global__ void hy_prep_x(const float* __restrict__ Q,
                          const float* __restrict__ curv, int B, int d) {
    int w = (blockIdx.x * blockDim.x + threadIdx.x) >> 5;
    int lane = threadIdx.x & 31;
    if (w >= B) return;
    const float* row = Q + (long)w * d;
    __nv_bfloat16* brow = g_Qb + (long)w * d;
    float s = 0.f;
    for (int k = lane * 4; k < d; k += 128) {
        float4 v = *reinterpret_cast<const float4*>(row + k);
        s += v.x*v.x + v.y*v.y + v.z*v.z + v.w*v.w;
        __nv_bfloat162* bp = reinterpret_cast<__nv_bfloat162*>(brow + k);
        bp[0] = __floats2bfloat162_rn(v.x, v.y);
        bp[1] = __floats2bfloat162_rn(v.z, v.w);
    }
    #pragma unroll
    for (int o = 16; o > 0; o >>= 1) s += __shfl_xor_sync(0xffffffffu, s, o);
    if (lane == 0) {
        float c  = curv[w];
        float xs = s;
        float sc = sqrtf(c + EPS);
        float Bq = 1.f - c * xs;
        float* rc = g_rowc + w * 8;
        rc[0] = c;  rc[1] = xs;  rc[2] = Bq;  rc[3] = Bq * Bq;
        rc[4] = c * c * xs;  rc[5] = sc;
        rc[6] = -1.f / (sc + EPS);
        rc[7] = 1.f / (sc + EPS) - EPS;
    }
}

// ===================== main HMMA fused kernel (128-thread CTA, 4 CTAs/SM) =====================
#define BM 64
#define BN 128
#define BK 32
#define RSB 80                 // padded row stride bytes (32 bf16 = 64B + 16 pad)
#define ATILE (BM * RSB)       // 5120
#define BTILE (BN * RSB)       // 10240

__global__ __launch_bounds__(128, 4)
void hy_mma(int B, int N, int d) {
    __shared__ __align__(16) char smA[2][ATILE];
    __shared__ __align__(16) char smB[2][BTILE];
    __shared__ float rc_s[BM * 8];
    __shared__ float ysq_s[BN];
    __shared__ float eb_s[BN];

    const int tid = threadIdx.x;
    const int wid = tid >> 5;
    const int lane = tid & 31;
    const int m0 = blockIdx.y * BM;
    const int n0 = blockIdx.x * BN;
    const int NKT = d / BK;

    const uint32_t sA0 = smem_u32(&smA[0][0]);
    const uint32_t sA1 = smem_u32(&smA[1][0]);
    const uint32_t sB0 = smem_u32(&smB[0][0]);
    const uint32_t sB1 = smem_u32(&smB[1][0]);

    // epilogue constants
    for (int idx = tid; idx < BM * 8; idx += 128) {
        int r = idx >> 3, cc = idx & 7, gm = m0 + r;
        rc_s[idx] = (gm < B) ? g_rowc[gm * 8 + cc] : 0.f;
    }
    for (int idx = tid; idx < BN; idx += 128) {
        int gn = n0 + idx;
        ysq_s[idx] = (gn < N) ? g_ysq[gn] : 0.f;
        eb_s[idx]  = (gn < N) ? g_eb[gn]  : 0.f;
    }

    // loader geometry: 16B chunks; A has 256 (2/thread), B has 512 (4/thread)
    const int lrow = tid >> 2;          // 0..31
    const int lc16 = tid & 3;

    // ---- prefetch k-chunk 0 ----
    {
        #pragma unroll
        for (int i = 0; i < 2; i++) {
            int row = lrow + i * 32;
            int gm = m0 + row; bool ok = gm < B;
            cp16(sA0 + row * RSB + lc16 * 16,
                 g_Qb + ((long)(ok ? gm : 0) * d + lc16 * 8), ok);
        }
        #pragma unroll
        for (int i = 0; i < 4; i++) {
            int row = lrow + i * 32;
            int gn = n0 + row; bool ok = gn < N;
            cp16(sB0 + row * RSB + lc16 * 16,
                 g_Cb + ((long)(ok ? gn : 0) * d + lc16 * 8), ok);
        }
        CP_COMMIT();
    }

    // warp tile: 32(m) x 64(n); 4 warps: 2x2
    const int wm = (wid & 1) * 32;
    const int wn = (wid >> 1) * 64;
    const uint32_t aoff = sA1 - sA0;
    const uint32_t boff = sB1 - sB0;
    const uint32_t a_base = sA0 + (wm + (lane & 15)) * RSB + (lane >> 4) * 16;
    const uint32_t b_base = sB0 + (wn + (lane >> 4) * 8 + (lane & 7)) * RSB
                               + ((lane >> 3) & 1) * 16;

    float acc[2][8][4];
    #pragma unroll
    for (int mi = 0; mi < 2; mi++)
        #pragma unroll
        for (int ni = 0; ni < 8; ni++)
            #pragma unroll
            for (int q = 0; q < 4; q++) acc[mi][ni][q] = 0.f;

    for (int kt = 0; kt < NKT; kt++) {
        const uint32_t abuf = (kt & 1) ? aoff : 0;
        const uint32_t bbuf = (kt & 1) ? boff : 0;

        if (kt + 1 < NKT) {
            const uint32_t na = ((kt + 1) & 1) ? aoff : 0;
            const uint32_t nb = ((kt + 1) & 1) ? boff : 0;
            #pragma unroll
            for (int i = 0; i < 2; i++) {
                int row = lrow + i * 32;
                int gm = m0 + row; bool ok = gm < B;
                cp16(sA0 + na + row * RSB + lc16 * 16,
                     g_Qb + ((long)(ok ? gm : 0) * d + (kt + 1) * BK + lc16 * 8), ok);
            }
            #pragma unroll
            for (int i = 0; i < 4; i++) {
                int row = lrow + i * 32;
                int gn = n0 + row; bool ok = gn < N;
                cp16(sB0 + nb + row * RSB + lc16 * 16,
                     g_Cb + ((long)(ok ? gn : 0) * d + (kt + 1) * BK + lc16 * 8), ok);
            }
            CP_COMMIT();
            CP_WAIT(1);
        } else {
            CP_WAIT(0);
        }
        __syncthreads();

        #pragma unroll
        for (int ks = 0; ks < 2; ks++) {
            uint32_t a[2][4];
            #pragma unroll
            for (int mi = 0; mi < 2; mi++)
                LDSM_X4(a[mi][0], a[mi][1], a[mi][2], a[mi][3],
                        a_base + abuf + mi * 16 * RSB + ks * 32);
            uint32_t b[4][4];
            #pragma unroll
            for (int g = 0; g < 4; g++)
                LDSM_X4(b[g][0], b[g][1], b[g][2], b[g][3],
                        b_base + bbuf + g * 16 * RSB + ks * 32);
            #pragma unroll
            for (int mi = 0; mi < 2; mi++)
                #pragma unroll
                for (int ni = 0; ni < 8; ni++)
                    MMA16816(acc[mi][ni], a[mi], b[ni >> 1][(ni & 1) * 2],
                             b[ni >> 1][(ni & 1) * 2 + 1]);
        }
        __syncthreads();
    }

    // ---------------- epilogue ----------------
    #pragma unroll
    for (int mi = 0; mi < 2; mi++) {
        #pragma unroll
        for (int half = 0; half < 2; half++) {
            const int mrow = wm + mi * 16 + half * 8 + (lane >> 2);
            const int gm = m0 + mrow;
            const float* rc = rc_s + mrow * 8;
            const float c    = rc[0];
            const float xs   = rc[1];
            const float Bq   = rc[2];
            const float Bq2  = rc[3];
            const float c2xs = rc[4];
            const float sc   = rc[5];
            const float p    = rc[6];
            const float maxn = rc[7];
            const float m2c  = -2.f * c;
            const float m2Bq = -2.f * Bq;

            float rowsum = 0.f;
            #pragma unroll
            for (int ni = 0; ni < 8; ni++) {
                #pragma unroll
                for (int q = 0; q < 2; q++) {
                    float u  = acc[mi][ni][half * 2 + q];
                    int col  = wn + ni * 8 + 2 * (lane & 3) + q;
                    float v  = ysq_s[col];
                    float eb = eb_s[col];
                    float t    = fmaf(-2.f, u, v);
                    float A    = fmaf(c, t, 1.f);
                    float denp = fmaf(c2xs, v, fmaf(m2c, u, 1.f)) + EPS;
                    float ns   = fmaf(Bq2, v, A * fmaf(m2Bq, u, A * xs));
                    float r0   = sqrtf(fmaxf(ns, 0.f));
                    r0 = fminf(fmaxf(r0, EPS * denp), maxn * denp);
                    float s    = sc * r0;
                    float ratio = __fdividef(denp + s, denp - s);   // (1+z)/(1-z)
                    rowsum = fmaf(eb, fast_ex2(p * fast_lg2(ratio)), rowsum);
                }
            }
            rowsum += __shfl_xor_sync(0xffffffffu, rowsum, 1);
            rowsum += __shfl_xor_sync(0xffffffffu, rowsum, 2);
            if ((lane & 3) == 0 && gm < B) atomicAdd(&g_sumexp[gm], rowsum);
        }
    }
}

// ===================== finalize =====================
__global__ void hy_finalize(const float* __restrict__ Q, const float* __restrict__ C,
                            const float* __restrict__ bias, const int* __restrict__ tgt,
                            float* out, int B, int N, int d) {
    int w = (blockIdx.x * blockDim.x + threadIdx.x) >> 5;
    int lane = threadIdx.x & 31;
    if (w >= B) return;
    int t = tgt[w];
    const float* q  = Q + (long)w * d;
    const float* cd = C + (long)t * d;
    float s = 0.f;
    for (int k = lane * 4; k < d; k += 128) {
        float4 a = *reinterpret_cast<const float4*>(q + k);
        float4 b = *reinterpret_cast<const float4*>(cd + k);
        s += a.x*b.x + a.y*b.y + a.z*b.z + a.w*b.w;
    }
    #pragma unroll
    for (int o = 16; o > 0; o >>= 1) s += __shfl_xor_sync(0xffffffffu, s, o);
    if (lane == 0) {
        const float* rc = g_rowc + w * 8;
        float c = rc[0], xs = rc[1], Bq = rc[2], Bq2 = rc[3], c2xs = rc[4];
        float sc = rc[5], maxn = rc[7];
        float u = s, v = g_ysq[t];
        float tt  = fmaf(-2.f, u, v);
        float A   = fmaf(c, tt, 1.f);
        float den = fmaf(c2xs, v, fmaf(-2.f * c, u, 1.f));
        float ns  = fmaf(Bq2, v, A * fmaf(-2.f * Bq, u, A * xs));
        float r   = sqrtf(fmaxf(ns, 0.f));
        float dn  = r / (den + EPS);
        dn = fminf(fmaxf(dn, EPS), maxn);
        float z = fminf(sc * dn, 1.f - EPS);
        float dist = (2.f / (sc + EPS)) * atanhf(z);
        float tlogit = bias[t] - dist;
        float lse = logf(g_sumexp[w]);
        atomicAdd(out, (lse - tlogit) * (1.f / (float)B));
    }
}

// ===================== launch =====================
extern "C" void kernel_launch(void* const* d_in, const int* in_sizes, int n_in,
                              void* d_out, int out_size) {
    const float* Q    = (const float*)d_in[0];
    const float* C    = (const float*)d_in[1];
    const float* bias = (const float*)d_in[2];
    const float* curv = (const float*)d_in[3];
    const int*   tgt  = (const int*)d_in[4];
    float* out = (float*)d_out;

    int B = in_sizes[3];
    int N = in_sizes[2];
    int d = in_sizes[0] / B;

    hy_init<<<(B + 255) / 256, 256>>>(out, B);
    hy_prep_y<<<(N * 32 + 255) / 256, 256>>>(C, bias, N, d);
    hy_prep_x<<<(B * 32 + 255) / 256, 256>>>(Q, curv, B, d);

    dim3 grid((N + BN - 1) / BN, (B + BM - 1) / BM);
    hy_mma<<<grid, 128>>>(B, N, d);

    hy_finalize<<<(B * 32 + 255) / 256, 256>>>(Q, C, bias, tgt, out, B, N, d);
}

// round 9
// speedup vs baseline: 1.4630x; 1.0488x over previous
#include <cuda_runtime.h>
#include <cuda_bf16.h>
#include <math.h>
#include <stdint.h>

#define EPS 1e-6f
#define MAXB 1024
#define MAXN 40000
#define MAXD 512

// ===================== fast math =====================
__device__ __forceinline__ float fast_lg2(float x) {
    float r; asm("lg2.approx.f32 %0, %1;" : "=f"(r) : "f"(x)); return r;
}
__device__ __forceinline__ float fast_ex2(float x) {
    float r; asm("ex2.approx.f32 %0, %1;" : "=f"(r) : "f"(x)); return r;
}
__device__ __forceinline__ uint32_t smem_u32(const void* p) {
    uint32_t a;
    asm("{ .reg .u64 t; cvta.to.shared.u64 t, %1; cvt.u32.u64 %0, t; }" : "=r"(a) : "l"(p));
    return a;
}

// ===================== mma.sync helpers =====================
#define LDSM_X4(r0, r1, r2, r3, addr)                                          \
    asm volatile("ldmatrix.sync.aligned.m8n8.x4.shared.b16 {%0,%1,%2,%3}, [%4];" \
        : "=r"(r0), "=r"(r1), "=r"(r2), "=r"(r3) : "r"(addr))

#define MMA16816(c, a, b0, b1)                                                 \
    asm volatile("mma.sync.aligned.m16n8k16.row.col.f32.bf16.bf16.f32 "        \
        "{%0,%1,%2,%3}, {%4,%5,%6,%7}, {%8,%9}, {%0,%1,%2,%3};"                \
        : "+f"((c)[0]), "+f"((c)[1]), "+f"((c)[2]), "+f"((c)[3])               \
        : "r"((a)[0]), "r"((a)[1]), "r"((a)[2]), "r"((a)[3]), "r"(b0), "r"(b1))

__device__ __forceinline__ void cp16(uint32_t dst, const void* src, bool pred) {
    int sz = pred ? 16 : 0;   // src-size 0 => zero-fill (keeps OOB tiles clean)
    asm volatile("cp.async.cg.shared.global [%0], [%1], 16, %2;"
        :: "r"(dst), "l"(src), "r"(sz) : "memory");
}
#define CP_COMMIT() asm volatile("cp.async.commit_group;" ::: "memory")
#define CP_WAIT(n)  asm volatile("cp.async.wait_group %0;" :: "n"(n) : "memory")

// ===================== scratch =====================
__device__ __align__(16) __nv_bfloat16 g_Qb[MAXB * MAXD];
__device__ __align__(16) __nv_bfloat16 g_Cb[MAXN * MAXD];
__device__ float g_ysq[MAXN];
__device__ float g_eb[MAXN];
__device__ float g_rowc[MAXB * 8];
__device__ float g_sumexp[MAXB];

// ===================== init =====================
__global__ void hy_init(float* out, int B) {
    int i = blockIdx.x * blockDim.x + threadIdx.x;
    if (i < B) g_sumexp[i] = 0.f;
    if (i == 0) out[0] = 0.f;
}

// ===================== prep candidates =====================
__global__ void hy_prep_y(const float* __restrict__ C,
                          const float* __restrict__ bias, int N, int d) {
    int w = (blockIdx.x * blockDim.x + threadIdx.x) >> 5;
    int lane = threadIdx.x & 31;
    if (w >= N) return;
    const float* row = C + (long)w * d;
    __nv_bfloat16* brow = g_Cb + (long)w * d;
    float s = 0.f;
    for (int k = lane * 4; k < d; k += 128) {
        float4 v = *reinterpret_cast<const float4*>(row + k);
        s += v.x*v.x + v.y*v.y + v.z*v.z + v.w*v.w;
        __nv_bfloat162* bp = reinterpret_cast<__nv_bfloat162*>(brow + k);
        bp[0] = __floats2bfloat162_rn(v.x, v.y);
        bp[1] = __floats2bfloat162_rn(v.z, v.w);
    }
    #pragma unroll
    for (int o = 16; o > 0; o >>= 1) s += __shfl_xor_sync(0xffffffffu, s, o);
    if (lane == 0) { g_ysq[w] = s; g_eb[w] = expf(bias[w]); }
}

// ===================== prep queries =====================
__global__ void hy_prep_x(const float* __restrict__ Q,
                          const float* __restrict__ curv, int B, int d) {
    int w = (blockIdx.x * blockDim.x + threadIdx.x) >> 5;
    int lane = threadIdx.x & 31;
    if (w >= B) return;
    const float* row = Q + (long)w * d;
    __nv_bfloat16* brow = g_Qb + (long)w * d;
    float s = 0.f;
    for (int k = lane * 4; k < d; k += 128) {
        float4 v = *reinterpret_cast<const float4*>(row + k);
        s += v.x*v.x + v.y*v.y + v.z*v.z + v.w*v.w;
        __nv_bfloat162* bp = reinterpret_cast<__nv_bfloat162*>(brow + k);
        bp[0] = __floats2bfloat162_rn(v.x, v.y);
        bp[1] = __floats2bfloat162_rn(v.z, v.w);
    }
    #pragma unroll
    for (int o = 16; o > 0; o >>= 1) s += __shfl_xor_sync(0xffffffffu, s, o);
    if (lane == 0) {
        float c  = curv[w];
        float xs = s;
        float sc = sqrtf(c + EPS);
        float Bq = 1.f - c * xs;
        float* rc = g_rowc + w * 8;
        rc[0] = c;  rc[1] = xs;  rc[2] = Bq;  rc[3] = Bq * Bq;
        rc[4] = c * c * xs;  rc[5] = sc;
        rc[6] = -1.f / (sc + EPS);
        rc[7] = 1.f / (sc + EPS) - EPS;
    }
}

// ===================== main HMMA fused kernel (128-thr CTA, 3-stage, 1 barrier/chunk) =====================
#define BM 64
#define BN 128
#define BK 32
#define RSB 80                      // padded row stride bytes (64B data + 16 pad)
#define ATILE (BM * RSB)            // 5120
#define BTILE (BN * RSB)            // 10240
#define STAGE_B (ATILE + BTILE)     // 15360
#define STAGES 3
#define RC_OFF  (STAGES * STAGE_B)            // 46080
#define YSQ_OFF (RC_OFF + BM * 8 * 4)         // 48128
#define EB_OFF  (YSQ_OFF + BN * 4)            // 48640
#define SMEM_TOT (EB_OFF + BN * 4)            // 49152

__global__ __launch_bounds__(128, 4)
void hy_mma(int B, int N, int d) {
    extern __shared__ __align__(16) char smem[];
    const uint32_t sb = smem_u32(smem);

    const int tid = threadIdx.x;
    const int wid = tid >> 5;
    const int lane = tid & 31;
    const int m0 = blockIdx.y * BM;
    const int n0 = blockIdx.x * BN;
    const int NKT = d / BK;

    float* rc_s  = reinterpret_cast<float*>(smem + RC_OFF);
    float* ysq_s = reinterpret_cast<float*>(smem + YSQ_OFF);
    float* eb_s  = reinterpret_cast<float*>(smem + EB_OFF);

    // epilogue constants
    for (int idx = tid; idx < BM * 8; idx += 128) {
        int r = idx >> 3, cc = idx & 7, gm = m0 + r;
        rc_s[idx] = (gm < B) ? g_rowc[gm * 8 + cc] : 0.f;
    }
    for (int idx = tid; idx < BN; idx += 128) {
        int gn = n0 + idx;
        ysq_s[idx] = (gn < N) ? g_ysq[gn] : 0.f;
        eb_s[idx]  = (gn < N) ? g_eb[gn]  : 0.f;
    }

    // loader geometry
    const int lrow = tid >> 2;          // 0..31
    const int lc16 = tid & 3;

    // prologue: prefetch stages 0 and 1
    #pragma unroll
    for (int s = 0; s < STAGES - 1; s++) {
        const uint32_t so = s * STAGE_B;
        #pragma unroll
        for (int i = 0; i < 2; i++) {
            int row = lrow + i * 32;
            int gm = m0 + row; bool ok = gm < B;
            cp16(sb + so + row * RSB + lc16 * 16,
                 g_Qb + ((long)(ok ? gm : 0) * d + s * BK + lc16 * 8), ok);
        }
        #pragma unroll
        for (int i = 0; i < 4; i++) {
            int row = lrow + i * 32;
            int gn = n0 + row; bool ok = gn < N;
            cp16(sb + so + ATILE + row * RSB + lc16 * 16,
                 g_Cb + ((long)(ok ? gn : 0) * d + s * BK + lc16 * 8), ok);
        }
        CP_COMMIT();
    }

    // warp tile: 32(m) x 64(n); 4 warps: 2x2
    const int wm = (wid & 1) * 32;
    const int wn = (wid >> 1) * 64;
    const uint32_t a_base = sb + (wm + (lane & 15)) * RSB + (lane >> 4) * 16;
    const uint32_t b_base = sb + ATILE + (wn + (lane >> 4) * 8 + (lane & 7)) * RSB
                               + ((lane >> 3) & 1) * 16;

    float acc[2][8][4];
    #pragma unroll
    for (int mi = 0; mi < 2; mi++)
        #pragma unroll
        for (int ni = 0; ni < 8; ni++)
            #pragma unroll
            for (int q = 0; q < 4; q++) acc[mi][ni][q] = 0.f;

    int sCur = 0;                    // stage of chunk kt
    for (int kt = 0; kt < NKT; kt++) {
        CP_WAIT(1);                  // group for chunk kt complete (2-iter slack)
        __syncthreads();             // data visible CTA-wide; prior readers of next write-target done

        // prefetch chunk kt+2 into stage (sCur+2)%3 == (sCur-1)%3
        if (kt + 2 < NKT) {
            int sNxt = sCur + 2; if (sNxt >= STAGES) sNxt -= STAGES;
            const uint32_t so = sNxt * STAGE_B;
            const int kk = (kt + 2) * BK;
            #pragma unroll
            for (int i = 0; i < 2; i++) {
                int row = lrow + i * 32;
                int gm = m0 + row; bool ok = gm < B;
                cp16(sb + so + row * RSB + lc16 * 16,
                     g_Qb + ((long)(ok ? gm : 0) * d + kk + lc16 * 8), ok);
            }
            #pragma unroll
            for (int i = 0; i < 4; i++) {
                int row = lrow + i * 32;
                int gn = n0 + row; bool ok = gn < N;
                cp16(sb + so + ATILE + row * RSB + lc16 * 16,
                     g_Cb + ((long)(ok ? gn : 0) * d + kk + lc16 * 8), ok);
            }
        }
        CP_COMMIT();                 // commit (possibly empty) to keep group accounting uniform

        const uint32_t so = sCur * STAGE_B;
        #pragma unroll
        for (int ks = 0; ks < 2; ks++) {
            uint32_t a[2][4];
            #pragma unroll
            for (int mi = 0; mi < 2; mi++)
                LDSM_X4(a[mi][0], a[mi][1], a[mi][2], a[mi][3],
                        a_base + so + mi * 16 * RSB + ks * 32);
            uint32_t b[4][4];
            #pragma unroll
            for (int g = 0; g < 4; g++)
                LDSM_X4(b[g][0], b[g][1], b[g][2], b[g][3],
                        b_base + so + g * 16 * RSB + ks * 32);
            #pragma unroll
            for (int mi = 0; mi < 2; mi++)
                #pragma unroll
                for (int ni = 0; ni < 8; ni++)
                    MMA16816(acc[mi][ni], a[mi], b[ni >> 1][(ni & 1) * 2],
                             b[ni >> 1][(ni & 1) * 2 + 1]);
        }
        if (++sCur >= STAGES) sCur -= STAGES;
    }

    // ---------------- epilogue ----------------
    #pragma unroll
    for (int mi = 0; mi < 2; mi++) {
        #pragma unroll
        for (int half = 0; half < 2; half++) {
            const int mrow = wm + mi * 16 + half * 8 + (lane >> 2);
            const int gm = m0 + mrow;
            const float* rc = rc_s + mrow * 8;
            const float c    = rc[0];
            const float xs   = rc[1];
            const float Bq   = rc[2];
            const float Bq2  = rc[3];
            const float c2xs = rc[4];
            const float sc   = rc[5];
            const float p    = rc[6];
            const float maxn = rc[7];
            const float m2c  = -2.f * c;
            const float m2Bq = -2.f * Bq;

            float rowsum = 0.f;
            #pragma unroll
            for (int ni = 0; ni < 8; ni++) {
                #pragma unroll
                for (int q = 0; q < 2; q++) {
                    float u  = acc[mi][ni][half * 2 + q];
                    int col  = wn + ni * 8 + 2 * (lane & 3) + q;
                    float v  = ysq_s[col];
                    float eb = eb_s[col];
                    float t    = fmaf(-2.f, u, v);
                    float A    = fmaf(c, t, 1.f);
                    float denp = fmaf(c2xs, v, fmaf(m2c, u, 1.f)) + EPS;
                    float ns   = fmaf(Bq2, v, A * fmaf(m2Bq, u, A * xs));
                    float r0   = sqrtf(fmaxf(ns, 0.f));
                    r0 = fminf(fmaxf(r0, EPS * denp), maxn * denp);
                    float s    = sc * r0;
                    float ratio = __fdividef(denp + s, denp - s);   // (1+z)/(1-z)
                    rowsum = fmaf(eb, fast_ex2(p * fast_lg2(ratio)), rowsum);
                }
            }
            rowsum += __shfl_xor_sync(0xffffffffu, rowsum, 1);
            rowsum += __shfl_xor_sync(0xffffffffu, rowsum, 2);
            if ((lane & 3) == 0 && gm < B) atomicAdd(&g_sumexp[gm], rowsum);
        }
    }
}

// ===================== finalize =====================
__global__ void hy_finalize(const float* __restrict__ Q, const float* __restrict__ C,
                            const float* __restrict__ bias, const int* __restrict__ tgt,
                            float* out, int B, int N, int d) {
    int w = (blockIdx.x * blockDim.x + threadIdx.x) >> 5;
    int lane = threadIdx.x & 31;
    if (w >= B) return;
    int t = tgt[w];
    const float* q  = Q + (long)w * d;
    const float* cd = C + (long)t * d;
    float s = 0.f;
    for (int k = lane * 4; k < d; k += 128) {
        float4 a = *reinterpret_cast<const float4*>(q + k);
        float4 b = *reinterpret_cast<const float4*>(cd + k);
        s += a.x*b.x + a.y*b.y + a.z*b.z + a.w*b.w;
    }
    #pragma unroll
    for (int o = 16; o > 0; o >>= 1) s += __shfl_xor_sync(0xffffffffu, s, o);
    if (lane == 0) {
        const float* rc = g_rowc + w * 8;
        float c = rc[0], xs = rc[1], Bq = rc[2], Bq2 = rc[3], c2xs = rc[4];
        float sc = rc[5], maxn = rc[7];
        float u = s, v = g_ysq[t];
        float tt  = fmaf(-2.f, u, v);
        float A   = fmaf(c, tt, 1.f);
        float den = fmaf(c2xs, v, fmaf(-2.f * c, u, 1.f));
        float ns  = fmaf(Bq2, v, A * fmaf(-2.f * Bq, u, A * xs));
        float r   = sqrtf(fmaxf(ns, 0.f));
        float dn  = r / (den + EPS);
        dn = fminf(fmaxf(dn, EPS), maxn);
        float z = fminf(sc * dn, 1.f - EPS);
        float dist = (2.f / (sc + EPS)) * atanhf(z);
        float tlogit = bias[t] - dist;
        float lse = logf(g_sumexp[w]);
        atomicAdd(out, (lse - tlogit) * (1.f / (float)B));
    }
}

// ===================== launch =====================
extern "C" void kernel_launch(void* const* d_in, const int* in_sizes, int n_in,
                              void* d_out, int out_size) {
    const float* Q    = (const float*)d_in[0];
    const float* C    = (const float*)d_in[1];
    const float* bias = (const float*)d_in[2];
    const float* curv = (const float*)d_in[3];
    const int*   tgt  = (const int*)d_in[4];
    float* out = (float*)d_out;

    int B = in_sizes[3];
    int N = in_sizes[2];
    int d = in_sizes[0] / B;

    hy_init<<<(B + 255) / 256, 256>>>(out, B);
    hy_prep_y<<<(N * 32 + 255) / 256, 256>>>(C, bias, N, d);
    hy_prep_x<<<(B * 32 + 255) / 256, 256>>>(Q, curv, B, d);

    cudaFuncSetAttribute(hy_mma, cudaFuncAttributeMaxDynamicSharedMemorySize, SMEM_TOT);
    dim3 grid((N + BN - 1) / BN, (B + BM - 1) / BM);
    hy_mma<<<grid, 128, SMEM_TOT>>>(B, N, d);

    hy_finalize<<<(B * 32 + 255) / 256, 256>>>(Q, C, bias, tgt, out, B, N, d);
}

// round 10
// speedup vs baseline: 1.5189x; 1.0382x over previous
#include <cuda_runtime.h>
#include <cuda_bf16.h>
#include <math.h>
#include <stdint.h>

#define EPS 1e-6f
#define MAXB 1024
#define MAXN 40000
#define MAXD 512

// ===================== fast math =====================
__device__ __forceinline__ float fast_lg2(float x) {
    float r; asm("lg2.approx.f32 %0, %1;" : "=f"(r) : "f"(x)); return r;
}
__device__ __forceinline__ float fast_ex2(float x) {
    float r; asm("ex2.approx.f32 %0, %1;" : "=f"(r) : "f"(x)); return r;
}
__device__ __forceinline__ uint32_t smem_u32(const void* p) {
    uint32_t a;
    asm("{ .reg .u64 t; cvta.to.shared.u64 t, %1; cvt.u32.u64 %0, t; }" : "=r"(a) : "l"(p));
    return a;
}

// ===================== mma.sync helpers =====================
#define LDSM_X4(r0, r1, r2, r3, addr)                                          \
    asm volatile("ldmatrix.sync.aligned.m8n8.x4.shared.b16 {%0,%1,%2,%3}, [%4];" \
        : "=r"(r0), "=r"(r1), "=r"(r2), "=r"(r3) : "r"(addr))

#define MMA16816(c, a, b0, b1)                                                 \
    asm volatile("mma.sync.aligned.m16n8k16.row.col.f32.bf16.bf16.f32 "        \
        "{%0,%1,%2,%3}, {%4,%5,%6,%7}, {%8,%9}, {%0,%1,%2,%3};"                \
        : "+f"((c)[0]), "+f"((c)[1]), "+f"((c)[2]), "+f"((c)[3])               \
        : "r"((a)[0]), "r"((a)[1]), "r"((a)[2]), "r"((a)[3]), "r"(b0), "r"(b1))

__device__ __forceinline__ void cp16(uint32_t dst, const void* src, bool pred) {
    int sz = pred ? 16 : 0;   // src-size 0 => zero-fill (keeps OOB tiles clean)
    asm volatile("cp.async.cg.shared.global [%0], [%1], 16, %2;"
        :: "r"(dst), "l"(src), "r"(sz) : "memory");
}
#define CP_COMMIT() asm volatile("cp.async.commit_group;" ::: "memory")
#define CP_WAIT(n)  asm volatile("cp.async.wait_group %0;" :: "n"(n) : "memory")

// ===================== scratch =====================
__device__ __align__(16) __nv_bfloat16 g_Qb[MAXB * MAXD];
__device__ __align__(16) __nv_bfloat16 g_Cb[MAXN * MAXD];
__device__ float g_ysq[MAXN];
__device__ float g_eb[MAXN];
__device__ float g_rowc[MAXB * 8];
__device__ float g_sumexp[MAXB];

// ===================== init =====================
__global__ void hy_init(float* out, int B) {
    int i = blockIdx.x * blockDim.x + threadIdx.x;
    if (i < B) g_sumexp[i] = 0.f;
    if (i == 0) out[0] = 0.f;
}

// ===================== prep candidates =====================
__global__ void hy_prep_y(const float* __restrict__ C,
                          const float* __restrict__ bias, int N, int d) {
    int w = (blockIdx.x * blockDim.x + threadIdx.x) >> 5;
    int lane = threadIdx.x & 31;
    if (w >= N) return;
    const float* row = C + (long)w * d;
    __nv_bfloat16* brow = g_Cb + (long)w * d;
    float s = 0.f;
    for (int k = lane * 4; k < d; k += 128) {
        float4 v = *reinterpret_cast<const float4*>(row + k);
        s += v.x*v.x + v.y*v.y + v.z*v.z + v.w*v.w;
        __nv_bfloat162* bp = reinterpret_cast<__nv_bfloat162*>(brow + k);
        bp[0] = __floats2bfloat162_rn(v.x, v.y);
        bp[1] = __floats2bfloat162_rn(v.z, v.w);
    }
    #pragma unroll
    for (int o = 16; o > 0; o >>= 1) s += __shfl_xor_sync(0xffffffffu, s, o);
    if (lane == 0) { g_ysq[w] = s; g_eb[w] = expf(bias[w]); }
}

// ===================== prep queries =====================
__global__ void hy_prep_x(const float* __restrict__ Q,
                          const float* __restrict__ curv, int B, int d) {
    int w = (blockIdx.x * blockDim.x + threadIdx.x) >> 5;
    int lane = threadIdx.x & 31;
    if (w >= B) return;
    const float* row = Q + (long)w * d;
    __nv_bfloat16* brow = g_Qb + (long)w * d;
    float s = 0.f;
    for (int k = lane * 4; k < d; k += 128) {
        float4 v = *reinterpret_cast<const float4*>(row + k);
        s += v.x*v.x + v.y*v.y + v.z*v.z + v.w*v.w;
        __nv_bfloat162* bp = reinterpret_cast<__nv_bfloat162*>(brow + k);
        bp[0] = __floats2bfloat162_rn(v.x, v.y);
        bp[1] = __floats2bfloat162_rn(v.z, v.w);
    }
    #pragma unroll
    for (int o = 16; o > 0; o >>= 1) s += __shfl_xor_sync(0xffffffffu, s, o);
    if (lane == 0) {
        float c  = curv[w];
        float xs = s;
        float sc = sqrtf(c + EPS);
        float Bq = 1.f - c * xs;
        float* rc = g_rowc + w * 8;
        rc[0] = c;  rc[1] = xs;  rc[2] = Bq;  rc[3] = Bq * Bq;
        rc[4] = c * c * xs;  rc[5] = sc;
        rc[6] = -1.f / (sc + EPS);
        rc[7] = 1.f / (sc + EPS) - EPS;
    }
}

// ===================== main HMMA fused kernel (128-thr CTA, 3-stage, 1 barrier/chunk) =====================
#define BM 64
#define BN 128
#define BK 32
#define RSB 80                      // padded row stride bytes (64B data + 16 pad)
#define ATILE (BM * RSB)            // 5120
#define BTILE (BN * RSB)            // 10240
#define STAGE_B (ATILE + BTILE)     // 15360
#define STAGES 3
#define RC_OFF  (STAGES * STAGE_B)            // 46080
#define YSQ_OFF (RC_OFF + BM * 8 * 4)         // 48128
#define EB_OFF  (YSQ_OFF + BN * 4)            // 48640
#define SMEM_TOT (EB_OFF + BN * 4)            // 49152

__global__ __launch_bounds__(128, 4)
void hy_mma(int B, int N, int d) {
    extern __shared__ __align__(16) char smem[];
    const uint32_t sb = smem_u32(smem);

    const int tid = threadIdx.x;
    const int wid = tid >> 5;
    const int lane = tid & 31;
    const int m0 = blockIdx.y * BM;
    const int n0 = blockIdx.x * BN;
    const int NKT = d / BK;

    float* rc_s  = reinterpret_cast<float*>(smem + RC_OFF);
    float* ysq_s = reinterpret_cast<float*>(smem + YSQ_OFF);
    float* eb_s  = reinterpret_cast<float*>(smem + EB_OFF);

    // epilogue constants
    for (int idx = tid; idx < BM * 8; idx += 128) {
        int r = idx >> 3, cc = idx & 7, gm = m0 + r;
        rc_s[idx] = (gm < B) ? g_rowc[gm * 8 + cc] : 0.f;
    }
    for (int idx = tid; idx < BN; idx += 128) {
        int gn = n0 + idx;
        ysq_s[idx] = (gn < N) ? g_ysq[gn] : 0.f;
        eb_s[idx]  = (gn < N) ? g_eb[gn]  : 0.f;
    }

    // ---- loader geometry: hoisted scalar pointers, OOB clamped once ----
    const int lrow = tid >> 2;          // 0..31
    const int lc16 = tid & 3;
    const int gmA0 = m0 + lrow,      gmA1 = m0 + lrow + 32;
    const bool okA0 = gmA0 < B,      okA1 = gmA1 < B;
    const int gnB0 = n0 + lrow,      gnB1 = n0 + lrow + 32;
    const int gnB2 = n0 + lrow + 64, gnB3 = n0 + lrow + 96;
    const bool okB0 = gnB0 < N, okB1 = gnB1 < N, okB2 = gnB2 < N, okB3 = gnB3 < N;
    // source pointers (advance by BK elements per chunk)
    const __nv_bfloat16* pA0 = g_Qb + (long)(okA0 ? gmA0 : 0) * d + lc16 * 8;
    const __nv_bfloat16* pA1 = g_Qb + (long)(okA1 ? gmA1 : 0) * d + lc16 * 8;
    const __nv_bfloat16* pB0 = g_Cb + (long)(okB0 ? gnB0 : 0) * d + lc16 * 8;
    const __nv_bfloat16* pB1 = g_Cb + (long)(okB1 ? gnB1 : 0) * d + lc16 * 8;
    const __nv_bfloat16* pB2 = g_Cb + (long)(okB2 ? gnB2 : 0) * d + lc16 * 8;
    const __nv_bfloat16* pB3 = g_Cb + (long)(okB3 ? gnB3 : 0) * d + lc16 * 8;
    // smem destination bases (stage 0; add stage offset per iter)
    const uint32_t dA0 = sb + lrow * RSB + lc16 * 16;
    const uint32_t dA1 = dA0 + 32 * RSB;
    const uint32_t dB0 = sb + ATILE + lrow * RSB + lc16 * 16;
    const uint32_t dB1 = dB0 + 32 * RSB;
    const uint32_t dB2 = dB0 + 64 * RSB;
    const uint32_t dB3 = dB0 + 96 * RSB;

    // prologue: prefetch stages 0 and 1 (chunks 0, 1)
    #pragma unroll
    for (int s = 0; s < STAGES - 1; s++) {
        const uint32_t so = s * STAGE_B;
        cp16(dA0 + so, pA0, okA0);  cp16(dA1 + so, pA1, okA1);
        cp16(dB0 + so, pB0, okB0);  cp16(dB1 + so, pB1, okB1);
        cp16(dB2 + so, pB2, okB2);  cp16(dB3 + so, pB3, okB3);
        CP_COMMIT();
        pA0 += BK; pA1 += BK; pB0 += BK; pB1 += BK; pB2 += BK; pB3 += BK;
    }
    // pointers now sit at chunk 2 == first in-loop prefetch target

    // warp tile: 32(m) x 64(n); 4 warps: 2x2
    const int wm = (wid & 1) * 32;
    const int wn = (wid >> 1) * 64;
    const uint32_t a_base = sb + (wm + (lane & 15)) * RSB + (lane >> 4) * 16;
    const uint32_t b_base = sb + ATILE + (wn + (lane >> 4) * 8 + (lane & 7)) * RSB
                               + ((lane >> 3) & 1) * 16;

    float acc[2][8][4];
    #pragma unroll
    for (int mi = 0; mi < 2; mi++)
        #pragma unroll
        for (int ni = 0; ni < 8; ni++)
            #pragma unroll
            for (int q = 0; q < 4; q++) acc[mi][ni][q] = 0.f;

    int sCur = 0;                    // stage of chunk kt
    for (int kt = 0; kt < NKT; kt++) {
        CP_WAIT(1);                  // group for chunk kt complete (2-iter slack)
        __syncthreads();             // data visible; prior readers of write-target done

        // prefetch chunk kt+2 into stage (sCur+2)%3
        if (kt + 2 < NKT) {
            int sNxt = sCur + 2; if (sNxt >= STAGES) sNxt -= STAGES;
            const uint32_t so = sNxt * STAGE_B;
            cp16(dA0 + so, pA0, okA0);  cp16(dA1 + so, pA1, okA1);
            cp16(dB0 + so, pB0, okB0);  cp16(dB1 + so, pB1, okB1);
            cp16(dB2 + so, pB2, okB2);  cp16(dB3 + so, pB3, okB3);
            pA0 += BK; pA1 += BK; pB0 += BK; pB1 += BK; pB2 += BK; pB3 += BK;
        }
        CP_COMMIT();                 // uniform group accounting

        const uint32_t so = sCur * STAGE_B;
        #pragma unroll
        for (int ks = 0; ks < 2; ks++) {
            uint32_t a[2][4];
            #pragma unroll
            for (int mi = 0; mi < 2; mi++)
                LDSM_X4(a[mi][0], a[mi][1], a[mi][2], a[mi][3],
                        a_base + so + mi * 16 * RSB + ks * 32);
            uint32_t b[4][4];
            #pragma unroll
            for (int g = 0; g < 4; g++)
                LDSM_X4(b[g][0], b[g][1], b[g][2], b[g][3],
                        b_base + so + g * 16 * RSB + ks * 32);
            #pragma unroll
            for (int mi = 0; mi < 2; mi++)
                #pragma unroll
                for (int ni = 0; ni < 8; ni++)
                    MMA16816(acc[mi][ni], a[mi], b[ni >> 1][(ni & 1) * 2],
                             b[ni >> 1][(ni & 1) * 2 + 1]);
        }
        if (++sCur >= STAGES) sCur -= STAGES;
    }

    // ---------------- epilogue ----------------
    #pragma unroll
    for (int mi = 0; mi < 2; mi++) {
        #pragma unroll
        for (int half = 0; half < 2; half++) {
            const int mrow = wm + mi * 16 + half * 8 + (lane >> 2);
            const int gm = m0 + mrow;
            const float* rc = rc_s + mrow * 8;
            const float c    = rc[0];
            const float xs   = rc[1];
            const float Bq   = rc[2];
            const float Bq2  = rc[3];
            const float c2xs = rc[4];
            const float sc   = rc[5];
            const float p    = rc[6];
            const float maxn = rc[7];
            const float m2c  = -2.f * c;
            const float m2Bq = -2.f * Bq;

            float rowsum = 0.f;
            #pragma unroll
            for (int ni = 0; ni < 8; ni++) {
                #pragma unroll
                for (int q = 0; q < 2; q++) {
                    float u  = acc[mi][ni][half * 2 + q];
                    int col  = wn + ni * 8 + 2 * (lane & 3) + q;
                    float v  = ysq_s[col];
                    float eb = eb_s[col];
                    float t    = fmaf(-2.f, u, v);
                    float A    = fmaf(c, t, 1.f);
                    float denp = fmaf(c2xs, v, fmaf(m2c, u, 1.f)) + EPS;
                    float ns   = fmaf(Bq2, v, A * fmaf(m2Bq, u, A * xs));
                    float r0   = sqrtf(fmaxf(ns, 0.f));
                    r0 = fminf(fmaxf(r0, EPS * denp), maxn * denp);
                    float s    = sc * r0;
                    float ratio = __fdividef(denp + s, denp - s);   // (1+z)/(1-z)
                    rowsum = fmaf(eb, fast_ex2(p * fast_lg2(ratio)), rowsum);
                }
            }
            rowsum += __shfl_xor_sync(0xffffffffu, rowsum, 1);
            rowsum += __shfl_xor_sync(0xffffffffu, rowsum, 2);
            if ((lane & 3) == 0 && gm < B) atomicAdd(&g_sumexp[gm], rowsum);
        }
    }
}

// ===================== finalize =====================
__global__ void hy_finalize(const float* __restrict__ Q, const float* __restrict__ C,
                            const float* __restrict__ bias, const int* __restrict__ tgt,
                            float* out, int B, int N, int d) {
    int w = (blockIdx.x * blockDim.x + threadIdx.x) >> 5;
    int lane = threadIdx.x & 31;
    if (w >= B) return;
    int t = tgt[w];
    const float* q  = Q + (long)w * d;
    const float* cd = C + (long)t * d;
    float s = 0.f;
    for (int k = lane * 4; k < d; k += 128) {
        float4 a = *reinterpret_cast<const float4*>(q + k);
        float4 b = *reinterpret_cast<const float4*>(cd + k);
        s += a.x*b.x + a.y*b.y + a.z*b.z + a.w*b.w;
    }
    #pragma unroll
    for (int o = 16; o > 0; o >>= 1) s += __shfl_xor_sync(0xffffffffu, s, o);
    if (lane == 0) {
        const float* rc = g_rowc + w * 8;
        float c = rc[0], xs = rc[1], Bq = rc[2], Bq2 = rc[3], c2xs = rc[4];
        float sc = rc[5], maxn = rc[7];
        float u = s, v = g_ysq[t];
        float tt  = fmaf(-2.f, u, v);
        float A   = fmaf(c, tt, 1.f);
        float den = fmaf(c2xs, v, fmaf(-2.f * c, u, 1.f));
        float ns  = fmaf(Bq2, v, A * fmaf(-2.f * Bq, u, A * xs));
        float r   = sqrtf(fmaxf(ns, 0.f));
        float dn  = r / (den + EPS);
        dn = fminf(fmaxf(dn, EPS), maxn);
        float z = fminf(sc * dn, 1.f - EPS);
        float dist = (2.f / (sc + EPS)) * atanhf(z);
        float tlogit = bias[t] - dist;
        float lse = logf(g_sumexp[w]);
        atomicAdd(out, (lse - tlogit) * (1.f / (float)B));
    }
}

// ===================== launch =====================
extern "C" void kernel_launch(void* const* d_in, const int* in_sizes, int n_in,
                              void* d_out, int out_size) {
    const float* Q    = (const float*)d_in[0];
    const float* C    = (const float*)d_in[1];
    const float* bias = (const float*)d_in[2];
    const float* curv = (const float*)d_in[3];
    const int*   tgt  = (const int*)d_in[4];
    float* out = (float*)d_out;

    int B = in_sizes[3];
    int N = in_sizes[2];
    int d = in_sizes[0] / B;

    hy_init<<<(B + 255) / 256, 256>>>(out, B);
    hy_prep_y<<<(N * 32 + 255) / 256, 256>>>(C, bias, N, d);
    hy_prep_x<<<(B * 32 + 255) / 256, 256>>>(Q, curv, B, d);

    cudaFuncSetAttribute(hy_mma, cudaFuncAttributeMaxDynamicSharedMemorySize, SMEM_TOT);
    dim3 grid((N + BN - 1) / BN, (B + BM - 1) / BM);
    hy_mma<<<grid, 128, SMEM_TOT>>>(B, N, d);

    hy_finalize<<<(B * 32 + 255) / 256, 256>>>(Q, C, bias, tgt, out, B, N, d);
}

// round 11
// speedup vs baseline: 1.5529x; 1.0224x over previous
#include <cuda_runtime.h>
#include <cuda_bf16.h>
#include <math.h>
#include <stdint.h>

#define EPS 1e-6f
#define MAXB 1024
#define MAXN 40000
#define MAXD 512

// ===================== fast math =====================
__device__ __forceinline__ float fast_lg2(float x) {
    float r; asm("lg2.approx.f32 %0, %1;" : "=f"(r) : "f"(x)); return r;
}
__device__ __forceinline__ float fast_ex2(float x) {
    float r; asm("ex2.approx.f32 %0, %1;" : "=f"(r) : "f"(x)); return r;
}
__device__ __forceinline__ uint32_t smem_u32(const void* p) {
    uint32_t a;
    asm("{ .reg .u64 t; cvta.to.shared.u64 t, %1; cvt.u32.u64 %0, t; }" : "=r"(a) : "l"(p));
    return a;
}

// ===================== mma.sync helpers =====================
#define LDSM_X4(r0, r1, r2, r3, addr)                                          \
    asm volatile("ldmatrix.sync.aligned.m8n8.x4.shared.b16 {%0,%1,%2,%3}, [%4];" \
        : "=r"(r0), "=r"(r1), "=r"(r2), "=r"(r3) : "r"(addr))

#define MMA16816(c, a, b0, b1)                                                 \
    asm volatile("mma.sync.aligned.m16n8k16.row.col.f32.bf16.bf16.f32 "        \
        "{%0,%1,%2,%3}, {%4,%5,%6,%7}, {%8,%9}, {%0,%1,%2,%3};"                \
        : "+f"((c)[0]), "+f"((c)[1]), "+f"((c)[2]), "+f"((c)[3])               \
        : "r"((a)[0]), "r"((a)[1]), "r"((a)[2]), "r"((a)[3]), "r"(b0), "r"(b1))

__device__ __forceinline__ void cp16(uint32_t dst, const void* src, bool pred) {
    int sz = pred ? 16 : 0;   // src-size 0 => zero-fill (keeps OOB tiles clean)
    asm volatile("cp.async.cg.shared.global [%0], [%1], 16, %2;"
        :: "r"(dst), "l"(src), "r"(sz) : "memory");
}
#define CP_COMMIT() asm volatile("cp.async.commit_group;" ::: "memory")
#define CP_WAIT(n)  asm volatile("cp.async.wait_group %0;" :: "n"(n) : "memory")

// ===================== scratch =====================
__device__ __align__(16) __nv_bfloat16 g_Qb[MAXB * MAXD];
__device__ __align__(16) __nv_bfloat16 g_Cb[MAXN * MAXD];
__device__ float g_ysq[MAXN];
__device__ float g_eb[MAXN];
__device__ float g_rowc[MAXB * 8];
__device__ float g_sumexp[MAXB];

// ===================== init =====================
__global__ void hy_init(float* out, int B) {
    int i = blockIdx.x * blockDim.x + threadIdx.x;
    if (i < B) g_sumexp[i] = 0.f;
    if (i == 0) out[0] = 0.f;
}

// ===================== prep candidates =====================
__global__ void hy_prep_y(const float* __restrict__ C,
                          const float* __restrict__ bias, int N, int d) {
    int w = (blockIdx.x * blockDim.x + threadIdx.x) >> 5;
    int lane = threadIdx.x & 31;
    if (w >= N) return;
    const float* row = C + (long)w * d;
    __nv_bfloat16* brow = g_Cb + (long)w * d;
    float s = 0.f;
    for (int k = lane * 4; k < d; k += 128) {
        float4 v = *reinterpret_cast<const float4*>(row + k);
        s += v.x*v.x + v.y*v.y + v.z*v.z + v.w*v.w;
        __nv_bfloat162* bp = reinterpret_cast<__nv_bfloat162*>(brow + k);
        bp[0] = __floats2bfloat162_rn(v.x, v.y);
        bp[1] = __floats2bfloat162_rn(v.z, v.w);
    }
    #pragma unroll
    for (int o = 16; o > 0; o >>= 1) s += __shfl_xor_sync(0xffffffffu, s, o);
    if (lane == 0) { g_ysq[w] = s; g_eb[w] = expf(bias[w]); }
}

// ===================== prep queries =====================
__global__ void hy_prep_x(const float* __restrict__ Q,
                          const float* __restrict__ curv, int B, int d) {
    int w = (blockIdx.x * blockDim.x + threadIdx.x) >> 5;
    int lane = threadIdx.x & 31;
    if (w >= B) return;
    const float* row = Q + (long)w * d;
    __nv_bfloat16* brow = g_Qb + (long)w * d;
    float s = 0.f;
    for (int k = lane * 4; k < d; k += 128) {
        float4 v = *reinterpret_cast<const float4*>(row + k);
        s += v.x*v.x + v.y*v.y + v.z*v.z + v.w*v.w;
        __nv_bfloat162* bp = reinterpret_cast<__nv_bfloat162*>(brow + k);
        bp[0] = __floats2bfloat162_rn(v.x, v.y);
        bp[1] = __floats2bfloat162_rn(v.z, v.w);
    }
    #pragma unroll
    for (int o = 16; o > 0; o >>= 1) s += __shfl_xor_sync(0xffffffffu, s, o);
    if (lane == 0) {
        float c  = curv[w];
        float xs = s;
        float sc = sqrtf(c + EPS);
        float Bq = 1.f - c * xs;
        float* rc = g_rowc + w * 8;
        rc[0] = c;  rc[1] = xs;  rc[2] = Bq;  rc[3] = Bq * Bq;
        rc[4] = c * c * xs;  rc[5] = sc;
        rc[6] = -1.f / (sc + EPS);
        rc[7] = 1.f / (sc + EPS) - EPS;
    }
}

// ===================== main HMMA fused kernel (256-thr CTA, BM=BN=128, 3-stage, 1 barrier/chunk) =====================
#define BM 128
#define BN 128
#define BK 32
#define RSB 80                      // padded row stride bytes (64B data + 16 pad)
#define ATILE (BM * RSB)            // 10240
#define BTILE (BN * RSB)            // 10240
#define STAGE_B (ATILE + BTILE)     // 20480
#define STAGES 3
#define RC_OFF  (STAGES * STAGE_B)            // 61440
#define YSQ_OFF (RC_OFF + BM * 8 * 4)         // 65536
#define EB_OFF  (YSQ_OFF + BN * 4)            // 66048
#define SMEM_TOT (EB_OFF + BN * 4)            // 66560

__global__ __launch_bounds__(256, 2)
void hy_mma(int B, int N, int d) {
    extern __shared__ __align__(16) char smem[];
    const uint32_t sb = smem_u32(smem);

    const int tid = threadIdx.x;
    const int wid = tid >> 5;
    const int lane = tid & 31;
    const int m0 = blockIdx.y * BM;
    const int n0 = blockIdx.x * BN;
    const int NKT = d / BK;

    float* rc_s  = reinterpret_cast<float*>(smem + RC_OFF);
    float* ysq_s = reinterpret_cast<float*>(smem + YSQ_OFF);
    float* eb_s  = reinterpret_cast<float*>(smem + EB_OFF);

    // epilogue constants
    for (int idx = tid; idx < BM * 8; idx += 256) {
        int r = idx >> 3, cc = idx & 7, gm = m0 + r;
        rc_s[idx] = (gm < B) ? g_rowc[gm * 8 + cc] : 0.f;
    }
    for (int idx = tid; idx < BN; idx += 256) {
        int gn = n0 + idx;
        ysq_s[idx] = (gn < N) ? g_ysq[gn] : 0.f;
        eb_s[idx]  = (gn < N) ? g_eb[gn]  : 0.f;
    }

    // ---- loader geometry: hoisted scalar pointers, OOB clamped once ----
    // 256 threads; each owns rows {r, r+64} of A and of B, one 16B column each
    const int lrow = tid >> 2;          // 0..63
    const int lc16 = tid & 3;
    const int gmA0 = m0 + lrow,      gmA1 = m0 + lrow + 64;
    const bool okA0 = gmA0 < B,      okA1 = gmA1 < B;
    const int gnB0 = n0 + lrow,      gnB1 = n0 + lrow + 64;
    const bool okB0 = gnB0 < N,      okB1 = gnB1 < N;
    const __nv_bfloat16* pA0 = g_Qb + (long)(okA0 ? gmA0 : 0) * d + lc16 * 8;
    const __nv_bfloat16* pA1 = g_Qb + (long)(okA1 ? gmA1 : 0) * d + lc16 * 8;
    const __nv_bfloat16* pB0 = g_Cb + (long)(okB0 ? gnB0 : 0) * d + lc16 * 8;
    const __nv_bfloat16* pB1 = g_Cb + (long)(okB1 ? gnB1 : 0) * d + lc16 * 8;
    const uint32_t dA0 = sb + lrow * RSB + lc16 * 16;
    const uint32_t dA1 = dA0 + 64 * RSB;
    const uint32_t dB0 = sb + ATILE + lrow * RSB + lc16 * 16;
    const uint32_t dB1 = dB0 + 64 * RSB;

    // prologue: prefetch stages 0 and 1 (chunks 0, 1)
    #pragma unroll
    for (int s = 0; s < STAGES - 1; s++) {
        const uint32_t so = s * STAGE_B;
        cp16(dA0 + so, pA0, okA0);  cp16(dA1 + so, pA1, okA1);
        cp16(dB0 + so, pB0, okB0);  cp16(dB1 + so, pB1, okB1);
        CP_COMMIT();
        pA0 += BK; pA1 += BK; pB0 += BK; pB1 += BK;
    }

    // warp tile: 32(m) x 64(n); 8 warps: 4(m) x 2(n)
    const int wm = (wid & 3) * 32;
    const int wn = (wid >> 2) * 64;
    const uint32_t a_base = sb + (wm + (lane & 15)) * RSB + (lane >> 4) * 16;
    const uint32_t b_base = sb + ATILE + (wn + (lane >> 4) * 8 + (lane & 7)) * RSB
                               + ((lane >> 3) & 1) * 16;

    float acc[2][8][4];
    #pragma unroll
    for (int mi = 0; mi < 2; mi++)
        #pragma unroll
        for (int ni = 0; ni < 8; ni++)
            #pragma unroll
            for (int q = 0; q < 4; q++) acc[mi][ni][q] = 0.f;

    int sCur = 0;
    for (int kt = 0; kt < NKT; kt++) {
        CP_WAIT(1);                  // chunk kt's group complete (2-iter slack)
        __syncthreads();

        // prefetch chunk kt+2 into stage (sCur+2)%3
        if (kt + 2 < NKT) {
            int sNxt = sCur + 2; if (sNxt >= STAGES) sNxt -= STAGES;
            const uint32_t so = sNxt * STAGE_B;
            cp16(dA0 + so, pA0, okA0);  cp16(dA1 + so, pA1, okA1);
            cp16(dB0 + so, pB0, okB0);  cp16(dB1 + so, pB1, okB1);
            pA0 += BK; pA1 += BK; pB0 += BK; pB1 += BK;
        }
        CP_COMMIT();

        const uint32_t so = sCur * STAGE_B;
        #pragma unroll
        for (int ks = 0; ks < 2; ks++) {
            uint32_t a[2][4];
            #pragma unroll
            for (int mi = 0; mi < 2; mi++)
                LDSM_X4(a[mi][0], a[mi][1], a[mi][2], a[mi][3],
                        a_base + so + mi * 16 * RSB + ks * 32);
            uint32_t b[4][4];
            #pragma unroll
            for (int g = 0; g < 4; g++)
                LDSM_X4(b[g][0], b[g][1], b[g][2], b[g][3],
                        b_base + so + g * 16 * RSB + ks * 32);
            #pragma unroll
            for (int mi = 0; mi < 2; mi++)
                #pragma unroll
                for (int ni = 0; ni < 8; ni++)
                    MMA16816(acc[mi][ni], a[mi], b[ni >> 1][(ni & 1) * 2],
                             b[ni >> 1][(ni & 1) * 2 + 1]);
        }
        if (++sCur >= STAGES) sCur -= STAGES;
    }

    // ---------------- epilogue ----------------
    #pragma unroll
    for (int mi = 0; mi < 2; mi++) {
        #pragma unroll
        for (int half = 0; half < 2; half++) {
            const int mrow = wm + mi * 16 + half * 8 + (lane >> 2);
            const int gm = m0 + mrow;
            const float* rc = rc_s + mrow * 8;
            const float c    = rc[0];
            const float xs   = rc[1];
            const float Bq   = rc[2];
            const float Bq2  = rc[3];
            const float c2xs = rc[4];
            const float sc   = rc[5];
            const float p    = rc[6];
            const float maxn = rc[7];
            const float m2c  = -2.f * c;
            const float m2Bq = -2.f * Bq;

            float rowsum = 0.f;
            #pragma unroll
            for (int ni = 0; ni < 8; ni++) {
                #pragma unroll
                for (int q = 0; q < 2; q++) {
                    float u  = acc[mi][ni][half * 2 + q];
                    int col  = wn + ni * 8 + 2 * (lane & 3) + q;
                    float v  = ysq_s[col];
                    float eb = eb_s[col];
                    float t    = fmaf(-2.f, u, v);
                    float A    = fmaf(c, t, 1.f);
                    float denp = fmaf(c2xs, v, fmaf(m2c, u, 1.f)) + EPS;
                    float ns   = fmaf(Bq2, v, A * fmaf(m2Bq, u, A * xs));
                    float r0   = sqrtf(fmaxf(ns, 0.f));
                    r0 = fminf(fmaxf(r0, EPS * denp), maxn * denp);
                    float s    = sc * r0;
                    float ratio = __fdividef(denp + s, denp - s);   // (1+z)/(1-z)
                    rowsum = fmaf(eb, fast_ex2(p * fast_lg2(ratio)), rowsum);
                }
            }
            rowsum += __shfl_xor_sync(0xffffffffu, rowsum, 1);
            rowsum += __shfl_xor_sync(0xffffffffu, rowsum, 2);
            if ((lane & 3) == 0 && gm < B) atomicAdd(&g_sumexp[gm], rowsum);
        }
    }
}

// ===================== finalize =====================
__global__ void hy_finalize(const float* __restrict__ Q, const float* __restrict__ C,
                            const float* __restrict__ bias, const int* __restrict__ tgt,
                            float* out, int B, int N, int d) {
    int w = (blockIdx.x * blockDim.x + threadIdx.x) >> 5;
    int lane = threadIdx.x & 31;
    if (w >= B) return;
    int t = tgt[w];
    const float* q  = Q + (long)w * d;
    const float* cd = C + (long)t * d;
    float s = 0.f;
    for (int k = lane * 4; k < d; k += 128) {
        float4 a = *reinterpret_cast<const float4*>(q + k);
        float4 b = *reinterpret_cast<const float4*>(cd + k);
        s += a.x*b.x + a.y*b.y + a.z*b.z + a.w*b.w;
    }
    #pragma unroll
    for (int o = 16; o > 0; o >>= 1) s += __shfl_xor_sync(0xffffffffu, s, o);
    if (lane == 0) {
        const float* rc = g_rowc + w * 8;
        float c = rc[0], xs = rc[1], Bq = rc[2], Bq2 = rc[3], c2xs = rc[4];
        float sc = rc[5], maxn = rc[7];
        float u = s, v = g_ysq[t];
        float tt  = fmaf(-2.f, u, v);
        float A   = fmaf(c, tt, 1.f);
        float den = fmaf(c2xs, v, fmaf(-2.f * c, u, 1.f));
        float ns  = fmaf(Bq2, v, A * fmaf(-2.f * Bq, u, A * xs));
        float r   = sqrtf(fmaxf(ns, 0.f));
        float dn  = r / (den + EPS);
        dn = fminf(fmaxf(dn, EPS), maxn);
        float z = fminf(sc * dn, 1.f - EPS);
        float dist = (2.f / (sc + EPS)) * atanhf(z);
        float tlogit = bias[t] - dist;
        float lse = logf(g_sumexp[w]);
        atomicAdd(out, (lse - tlogit) * (1.f / (float)B));
    }
}

// ===================== launch =====================
extern "C" void kernel_launch(void* const* d_in, const int* in_sizes, int n_in,
                              void* d_out, int out_size) {
    const float* Q    = (const float*)d_in[0];
    const float* C    = (const float*)d_in[1];
    const float* bias = (const float*)d_in[2];
    const float* curv = (const float*)d_in[3];
    const int*   tgt  = (const int*)d_in[4];
    float* out = (float*)d_out;

    int B = in_sizes[3];
    int N = in_sizes[2];
    int d = in_sizes[0] / B;

    hy_init<<<(B + 255) / 256, 256>>>(out, B);
    hy_prep_y<<<(N * 32 + 255) / 256, 256>>>(C, bias, N, d);
    hy_prep_x<<<(B * 32 + 255) / 256, 256>>>(Q, curv, B, d);

    cudaFuncSetAttribute(hy_mma, cudaFuncAttributeMaxDynamicSharedMemorySize, SMEM_TOT);
    dim3 grid((N + BN - 1) / BN, (B + BM - 1) / BM);
    hy_mma<<<grid, 256, SMEM_TOT>>>(B, N, d);

    hy_finalize<<<(B * 32 + 255) / 256, 256>>>(Q, C, bias, tgt, out, B, N, d);
}

// round 12
// speedup vs baseline: 1.5684x; 1.0100x over previous
#include <cuda_runtime.h>
#include <cuda_bf16.h>
#include <math.h>
#include <stdint.h>

#define EPS 1e-6f
#define MAXB 1024
#define MAXN 40000
#define MAXD 512

// ===================== fast math =====================
__device__ __forceinline__ float fast_lg2(float x) {
    float r; asm("lg2.approx.f32 %0, %1;" : "=f"(r) : "f"(x)); return r;
}
__device__ __forceinline__ float fast_ex2(float x) {
    float r; asm("ex2.approx.f32 %0, %1;" : "=f"(r) : "f"(x)); return r;
}
__device__ __forceinline__ uint32_t smem_u32(const void* p) {
    uint32_t a;
    asm("{ .reg .u64 t; cvta.to.shared.u64 t, %1; cvt.u32.u64 %0, t; }" : "=r"(a) : "l"(p));
    return a;
}

// ===================== mma.sync helpers =====================
#define LDSM_X4(r0, r1, r2, r3, addr)                                          \
    asm volatile("ldmatrix.sync.aligned.m8n8.x4.shared.b16 {%0,%1,%2,%3}, [%4];" \
        : "=r"(r0), "=r"(r1), "=r"(r2), "=r"(r3) : "r"(addr))

#define MMA16816(c, a, b0, b1)                                                 \
    asm volatile("mma.sync.aligned.m16n8k16.row.col.f32.bf16.bf16.f32 "        \
        "{%0,%1,%2,%3}, {%4,%5,%6,%7}, {%8,%9}, {%0,%1,%2,%3};"                \
        : "+f"((c)[0]), "+f"((c)[1]), "+f"((c)[2]), "+f"((c)[3])               \
        : "r"((a)[0]), "r"((a)[1]), "r"((a)[2]), "r"((a)[3]), "r"(b0), "r"(b1))

__device__ __forceinline__ void cp16(uint32_t dst, const void* src, bool pred) {
    int sz = pred ? 16 : 0;   // src-size 0 => zero-fill (keeps OOB tiles clean)
    asm volatile("cp.async.cg.shared.global [%0], [%1], 16, %2;"
        :: "r"(dst), "l"(src), "r"(sz) : "memory");
}
#define CP_COMMIT() asm volatile("cp.async.commit_group;" ::: "memory")
#define CP_WAIT(n)  asm volatile("cp.async.wait_group %0;" :: "n"(n) : "memory")

// ===================== scratch =====================
__device__ __align__(16) __nv_bfloat16 g_Qb[MAXB * MAXD];
__device__ __align__(16) __nv_bfloat16 g_Cb[MAXN * MAXD];
__device__ float g_ysq[MAXN];
__device__ float g_eb[MAXN];
__device__ float g_rowc[MAXB * 8];
__device__ float g_sumexp[MAXB];

// ===================== init =====================
__global__ void hy_init(float* out, int B) {
    int i = blockIdx.x * blockDim.x + threadIdx.x;
    if (i < B) g_sumexp[i] = 0.f;
    if (i == 0) out[0] = 0.f;
}

// ===================== prep candidates =====================
__global__ void hy_prep_y(const float* __restrict__ C,
                          const float* __restrict__ bias, int N, int d) {
    int w = (blockIdx.x * blockDim.x + threadIdx.x) >> 5;
    int lane = threadIdx.x & 31;
    if (w >= N) return;
    const float* row = C + (long)w * d;
    __nv_bfloat16* brow = g_Cb + (long)w * d;
    float s = 0.f;
    for (int k = lane * 4; k < d; k += 128) {
        float4 v = *reinterpret_cast<const float4*>(row + k);
        s += v.x*v.x + v.y*v.y + v.z*v.z + v.w*v.w;
        __nv_bfloat162* bp = reinterpret_cast<__nv_bfloat162*>(brow + k);
        bp[0] = __floats2bfloat162_rn(v.x, v.y);
        bp[1] = __floats2bfloat162_rn(v.z, v.w);
    }
    #pragma unroll
    for (int o = 16; o > 0; o >>= 1) s += __shfl_xor_sync(0xffffffffu, s, o);
    if (lane == 0) { g_ysq[w] = s; g_eb[w] = expf(bias[w]); }
}

// ===================== prep queries =====================
__global__ void hy_prep_x(const float* __restrict__ Q,
                          const float* __restrict__ curv, int B, int d) {
    int w = (blockIdx.x * blockDim.x + threadIdx.x) >> 5;
    int lane = threadIdx.x & 31;
    if (w >= B) return;
    const float* row = Q + (long)w * d;
    __nv_bfloat16* brow = g_Qb + (long)w * d;
    float s = 0.f;
    for (int k = lane * 4; k < d; k += 128) {
        float4 v = *reinterpret_cast<const float4*>(row + k);
        s += v.x*v.x + v.y*v.y + v.z*v.z + v.w*v.w;
        __nv_bfloat162* bp = reinterpret_cast<__nv_bfloat162*>(brow + k);
        bp[0] = __floats2bfloat162_rn(v.x, v.y);
        bp[1] = __floats2bfloat162_rn(v.z, v.w);
    }
    #pragma unroll
    for (int o = 16; o > 0; o >>= 1) s += __shfl_xor_sync(0xffffffffu, s, o);
    if (lane == 0) {
        float c  = curv[w];
        float xs = s;
        float sc = sqrtf(c + EPS);
        float Bq = 1.f - c * xs;
        float* rc = g_rowc + w * 8;
        rc[0] = c;  rc[1] = xs;  rc[2] = Bq;  rc[3] = Bq * Bq;
        rc[4] = c * c * xs;  rc[5] = sc;
        rc[6] = -1.f / (sc + EPS);
        rc[7] = 1.f / (sc + EPS) - EPS;
    }
}

// ===================== main HMMA fused kernel (256 thr, 32x32 warp tiles, 3 CTAs/SM) =====================
#define BM 64
#define BN 128
#define BK 32
#define RSB 80                      // padded row stride bytes (64B data + 16 pad)
#define ATILE (BM * RSB)            // 5120
#define BTILE (BN * RSB)            // 10240
#define STAGE_B (ATILE + BTILE)     // 15360
#define STAGES 3
#define RC_OFF  (STAGES * STAGE_B)            // 46080
#define YSQ_OFF (RC_OFF + BM * 8 * 4)         // 48128
#define EB_OFF  (YSQ_OFF + BN * 4)            // 48640
#define SMEM_TOT (EB_OFF + BN * 4)            // 49152

__global__ __launch_bounds__(256, 3)
void hy_mma(int B, int N, int d) {
    extern __shared__ __align__(16) char smem[];
    const uint32_t sb = smem_u32(smem);

    const int tid = threadIdx.x;
    const int wid = tid >> 5;
    const int lane = tid & 31;
    const int m0 = blockIdx.y * BM;
    const int n0 = blockIdx.x * BN;
    const int NKT = d / BK;

    float* rc_s  = reinterpret_cast<float*>(smem + RC_OFF);
    float* ysq_s = reinterpret_cast<float*>(smem + YSQ_OFF);
    float* eb_s  = reinterpret_cast<float*>(smem + EB_OFF);

    // epilogue constants
    for (int idx = tid; idx < BM * 8; idx += 256) {
        int r = idx >> 3, cc = idx & 7, gm = m0 + r;
        rc_s[idx] = (gm < B) ? g_rowc[gm * 8 + cc] : 0.f;
    }
    for (int idx = tid; idx < BN; idx += 256) {
        int gn = n0 + idx;
        ysq_s[idx] = (gn < N) ? g_ysq[gn] : 0.f;
        eb_s[idx]  = (gn < N) ? g_eb[gn]  : 0.f;
    }

    // ---- loader: A 64 rows (1 chunk/thread), B 128 rows (2 chunks/thread) ----
    const int lrow = tid >> 2;          // 0..63
    const int lc16 = tid & 3;
    const int gmA0 = m0 + lrow;
    const bool okA0 = gmA0 < B;
    const int gnB0 = n0 + lrow,  gnB1 = n0 + lrow + 64;
    const bool okB0 = gnB0 < N,  okB1 = gnB1 < N;
    const __nv_bfloat16* pA0 = g_Qb + (long)(okA0 ? gmA0 : 0) * d + lc16 * 8;
    const __nv_bfloat16* pB0 = g_Cb + (long)(okB0 ? gnB0 : 0) * d + lc16 * 8;
    const __nv_bfloat16* pB1 = g_Cb + (long)(okB1 ? gnB1 : 0) * d + lc16 * 8;
    const uint32_t dA0 = sb + lrow * RSB + lc16 * 16;
    const uint32_t dB0 = sb + ATILE + lrow * RSB + lc16 * 16;
    const uint32_t dB1 = dB0 + 64 * RSB;

    // prologue: prefetch stages 0 and 1 (chunks 0, 1)
    #pragma unroll
    for (int s = 0; s < STAGES - 1; s++) {
        const uint32_t so = s * STAGE_B;
        cp16(dA0 + so, pA0, okA0);
        cp16(dB0 + so, pB0, okB0);  cp16(dB1 + so, pB1, okB1);
        CP_COMMIT();
        pA0 += BK; pB0 += BK; pB1 += BK;
    }

    // warp tile: 32(m) x 32(n); 8 warps: 2(m) x 4(n)
    const int wm = (wid & 1) * 32;
    const int wn = (wid >> 1) * 32;
    const uint32_t a_base = sb + (wm + (lane & 15)) * RSB + (lane >> 4) * 16;
    const uint32_t b_base = sb + ATILE + (wn + (lane >> 4) * 8 + (lane & 7)) * RSB
                               + ((lane >> 3) & 1) * 16;

    float acc[2][4][4];
    #pragma unroll
    for (int mi = 0; mi < 2; mi++)
        #pragma unroll
        for (int ni = 0; ni < 4; ni++)
            #pragma unroll
            for (int q = 0; q < 4; q++) acc[mi][ni][q] = 0.f;

    int sCur = 0;
    for (int kt = 0; kt < NKT; kt++) {
        CP_WAIT(1);                  // chunk kt's group complete (2-iter slack)
        __syncthreads();

        // prefetch chunk kt+2 into stage (sCur+2)%3
        if (kt + 2 < NKT) {
            int sNxt = sCur + 2; if (sNxt >= STAGES) sNxt -= STAGES;
            const uint32_t so = sNxt * STAGE_B;
            cp16(dA0 + so, pA0, okA0);
            cp16(dB0 + so, pB0, okB0);  cp16(dB1 + so, pB1, okB1);
            pA0 += BK; pB0 += BK; pB1 += BK;
        }
        CP_COMMIT();

        const uint32_t so = sCur * STAGE_B;
        #pragma unroll
        for (int ks = 0; ks < 2; ks++) {
            uint32_t a[2][4];
            #pragma unroll
            for (int mi = 0; mi < 2; mi++)
                LDSM_X4(a[mi][0], a[mi][1], a[mi][2], a[mi][3],
                        a_base + so + mi * 16 * RSB + ks * 32);
            uint32_t b[2][4];   // [g][0,1]=n-tile 2g ; [g][2,3]=n-tile 2g+1
            #pragma unroll
            for (int g = 0; g < 2; g++)
                LDSM_X4(b[g][0], b[g][1], b[g][2], b[g][3],
                        b_base + so + g * 16 * RSB + ks * 32);
            #pragma unroll
            for (int mi = 0; mi < 2; mi++)
                #pragma unroll
                for (int ni = 0; ni < 4; ni++)
                    MMA16816(acc[mi][ni], a[mi], b[ni >> 1][(ni & 1) * 2],
                             b[ni >> 1][(ni & 1) * 2 + 1]);
        }
        if (++sCur >= STAGES) sCur -= STAGES;
    }

    // ---------------- epilogue ----------------
    #pragma unroll
    for (int mi = 0; mi < 2; mi++) {
        #pragma unroll
        for (int half = 0; half < 2; half++) {
            const int mrow = wm + mi * 16 + half * 8 + (lane >> 2);
            const int gm = m0 + mrow;
            const float* rc = rc_s + mrow * 8;
            const float c    = rc[0];
            const float xs   = rc[1];
            const float Bq   = rc[2];
            const float Bq2  = rc[3];
            const float c2xs = rc[4];
            const float sc   = rc[5];
            const float p    = rc[6];
            const float maxn = rc[7];
            const float m2c  = -2.f * c;
            const float m2Bq = -2.f * Bq;

            float rowsum = 0.f;
            #pragma unroll
            for (int ni = 0; ni < 4; ni++) {
                #pragma unroll
                for (int q = 0; q < 2; q++) {
                    float u  = acc[mi][ni][half * 2 + q];
                    int col  = wn + ni * 8 + 2 * (lane & 3) + q;
                    float v  = ysq_s[col];
                    float eb = eb_s[col];
                    float t    = fmaf(-2.f, u, v);
                    float A    = fmaf(c, t, 1.f);
                    float denp = fmaf(c2xs, v, fmaf(m2c, u, 1.f)) + EPS;
                    float ns   = fmaf(Bq2, v, A * fmaf(m2Bq, u, A * xs));
                    float r0   = sqrtf(fmaxf(ns, 0.f));
                    r0 = fminf(fmaxf(r0, EPS * denp), maxn * denp);
                    float s    = sc * r0;
                    float ratio = __fdividef(denp + s, denp - s);   // (1+z)/(1-z)
                    rowsum = fmaf(eb, fast_ex2(p * fast_lg2(ratio)), rowsum);
                }
            }
            rowsum += __shfl_xor_sync(0xffffffffu, rowsum, 1);
            rowsum += __shfl_xor_sync(0xffffffffu, rowsum, 2);
            if ((lane & 3) == 0 && gm < B) atomicAdd(&g_sumexp[gm], rowsum);
        }
    }
}

// ===================== finalize =====================
__global__ void hy_finalize(const float* __restrict__ Q, const float* __restrict__ C,
                            const float* __restrict__ bias, const int* __restrict__ tgt,
                            float* out, int B, int N, int d) {
    int w = (blockIdx.x * blockDim.x + threadIdx.x) >> 5;
    int lane = threadIdx.x & 31;
    if (w >= B) return;
    int t = tgt[w];
    const float* q  = Q + (long)w * d;
    const float* cd = C + (long)t * d;
    float s = 0.f;
    for (int k = lane * 4; k < d; k += 128) {
        float4 a = *reinterpret_cast<const float4*>(q + k);
        float4 b = *reinterpret_cast<const float4*>(cd + k);
        s += a.x*b.x + a.y*b.y + a.z*b.z + a.w*b.w;
    }
    #pragma unroll
    for (int o = 16; o > 0; o >>= 1) s += __shfl_xor_sync(0xffffffffu, s, o);
    if (lane == 0) {
        const float* rc = g_rowc + w * 8;
        float c = rc[0], xs = rc[1], Bq = rc[2], Bq2 = rc[3], c2xs = rc[4];
        float sc = rc[5], maxn = rc[7];
        float u = s, v = g_ysq[t];
        float tt  = fmaf(-2.f, u, v);
        float A   = fmaf(c, tt, 1.f);
        float den = fmaf(c2xs, v, fmaf(-2.f * c, u, 1.f));
        float ns  = fmaf(Bq2, v, A * fmaf(-2.f * Bq, u, A * xs));
        float r   = sqrtf(fmaxf(ns, 0.f));
        float dn  = r / (den + EPS);
        dn = fminf(fmaxf(dn, EPS), maxn);
        float z = fminf(sc * dn, 1.f - EPS);
        float dist = (2.f / (sc + EPS)) * atanhf(z);
        float tlogit = bias[t] - dist;
        float lse = logf(g_sumexp[w]);
        atomicAdd(out, (lse - tlogit) * (1.f / (float)B));
    }
}

// ===================== launch =====================
extern "C" void kernel_launch(void* const* d_in, const int* in_sizes, int n_in,
                              void* d_out, int out_size) {
    const float* Q    = (const float*)d_in[0];
    const float* C    = (const float*)d_in[1];
    const float* bias = (const float*)d_in[2];
    const float* curv = (const float*)d_in[3];
    const int*   tgt  = (const int*)d_in[4];
    float* out = (float*)d_out;

    int B = in_sizes[3];
    int N = in_sizes[2];
    int d = in_sizes[0] / B;

    hy_init<<<(B + 255) / 256, 256>>>(out, B);
    hy_prep_y<<<(N * 32 + 255) / 256, 256>>>(C, bias, N, d);
    hy_prep_x<<<(B * 32 + 255) / 256, 256>>>(Q, curv, B, d);

    cudaFuncSetAttribute(hy_mma, cudaFuncAttributeMaxDynamicSharedMemorySize, SMEM_TOT);
    dim3 grid((N + BN - 1) / BN, (B + BM - 1) / BM);
    hy_mma<<<grid, 256, SMEM_TOT>>>(B, N, d);

    hy_finalize<<<(B * 32 + 255) / 256, 256>>>(Q, C, bias, tgt, out, B, N, d);
}

// round 13
// speedup vs baseline: 1.6195x; 1.0325x over previous
#include <cuda_runtime.h>
#include <cuda_bf16.h>
#include <math.h>
#include <stdint.h>

#define EPS 1e-6f
#define MAXB 1024
#define MAXN 40000
#define MAXD 512

// ===================== fast math =====================
__device__ __forceinline__ float fast_lg2(float x) {
    float r; asm("lg2.approx.f32 %0, %1;" : "=f"(r) : "f"(x)); return r;
}
__device__ __forceinline__ float fast_ex2(float x) {
    float r; asm("ex2.approx.f32 %0, %1;" : "=f"(r) : "f"(x)); return r;
}
__device__ __forceinline__ uint32_t smem_u32(const void* p) {
    uint32_t a;
    asm("{ .reg .u64 t; cvta.to.shared.u64 t, %1; cvt.u32.u64 %0, t; }" : "=r"(a) : "l"(p));
    return a;
}

// ===================== mma.sync helpers =====================
#define LDSM_X4(r0, r1, r2, r3, addr)                                          \
    asm volatile("ldmatrix.sync.aligned.m8n8.x4.shared.b16 {%0,%1,%2,%3}, [%4];" \
        : "=r"(r0), "=r"(r1), "=r"(r2), "=r"(r3) : "r"(addr))

#define MMA16816(c, a, b0, b1)                                                 \
    asm volatile("mma.sync.aligned.m16n8k16.row.col.f32.bf16.bf16.f32 "        \
        "{%0,%1,%2,%3}, {%4,%5,%6,%7}, {%8,%9}, {%0,%1,%2,%3};"                \
        : "+f"((c)[0]), "+f"((c)[1]), "+f"((c)[2]), "+f"((c)[3])               \
        : "r"((a)[0]), "r"((a)[1]), "r"((a)[2]), "r"((a)[3]), "r"(b0), "r"(b1))

__device__ __forceinline__ void cp16(uint32_t dst, const void* src, bool pred) {
    int sz = pred ? 16 : 0;   // src-size 0 => zero-fill (keeps OOB tiles clean)
    asm volatile("cp.async.cg.shared.global [%0], [%1], 16, %2;"
        :: "r"(dst), "l"(src), "r"(sz) : "memory");
}
#define CP_COMMIT() asm volatile("cp.async.commit_group;" ::: "memory")
#define CP_WAIT(n)  asm volatile("cp.async.wait_group %0;" :: "n"(n) : "memory")

// ===================== scratch =====================
__device__ __align__(16) __nv_bfloat16 g_Qb[MAXB * MAXD];
__device__ __align__(16) __nv_bfloat16 g_Cb[MAXN * MAXD];
__device__ float g_ysq[MAXN];
__device__ float g_eb[MAXN];
__device__ float g_rowc[MAXB * 8];
__device__ float g_sumexp[MAXB];

// ===================== fused prep: init + candidates + queries =====================
__global__ void hy_prep(const float* __restrict__ Q, const float* __restrict__ C,
                        const float* __restrict__ bias, const float* __restrict__ curv,
                        float* out, int B, int N, int d) {
    const int gtid = blockIdx.x * blockDim.x + threadIdx.x;
    const int w = gtid >> 5;
    const int lane = gtid & 31;
    if (gtid < B) g_sumexp[gtid] = 0.f;
    if (gtid == 0) out[0] = 0.f;

    if (w < N) {
        // candidate row w: ysq, exp(bias), bf16 convert
        const float* row = C + (long)w * d;
        __nv_bfloat16* brow = g_Cb + (long)w * d;
        float s = 0.f;
        for (int k = lane * 4; k < d; k += 128) {
            float4 v = *reinterpret_cast<const float4*>(row + k);
            s += v.x*v.x + v.y*v.y + v.z*v.z + v.w*v.w;
            __nv_bfloat162* bp = reinterpret_cast<__nv_bfloat162*>(brow + k);
            bp[0] = __floats2bfloat162_rn(v.x, v.y);
            bp[1] = __floats2bfloat162_rn(v.z, v.w);
        }
        #pragma unroll
        for (int o = 16; o > 0; o >>= 1) s += __shfl_xor_sync(0xffffffffu, s, o);
        if (lane == 0) { g_ysq[w] = s; g_eb[w] = expf(bias[w]); }
    } else if (w < N + B) {
        // query row
        const int q = w - N;
        const float* row = Q + (long)q * d;
        __nv_bfloat16* brow = g_Qb + (long)q * d;
        float s = 0.f;
        for (int k = lane * 4; k < d; k += 128) {
            float4 v = *reinterpret_cast<const float4*>(row + k);
            s += v.x*v.x + v.y*v.y + v.z*v.z + v.w*v.w;
            __nv_bfloat162* bp = reinterpret_cast<__nv_bfloat162*>(brow + k);
            bp[0] = __floats2bfloat162_rn(v.x, v.y);
            bp[1] = __floats2bfloat162_rn(v.z, v.w);
        }
        #pragma unroll
        for (int o = 16; o > 0; o >>= 1) s += __shfl_xor_sync(0xffffffffu, s, o);
        if (lane == 0) {
            float c  = curv[q];
            float xs = s;
            float sc = sqrtf(c + EPS);
            float Bq = 1.f - c * xs;
            float* rc = g_rowc + q * 8;
            rc[0] = c;  rc[1] = xs;  rc[2] = Bq;  rc[3] = Bq * Bq;
            rc[4] = c * c * xs;  rc[5] = sc;
            rc[6] = -1.f / (sc + EPS);
            rc[7] = 1.f / (sc + EPS) - EPS;
        }
    }
}

// ===================== main HMMA fused kernel (4-stage const-folded, 24 warps/SM) =====================
#define BM 64
#define BN 128
#define BK 32
#define RSB 80                      // padded row stride bytes (64B data + 16 pad)
#define ATILE (BM * RSB)            // 5120
#define BTILE (BN * RSB)            // 10240
#define STAGE_B (ATILE + BTILE)     // 15360
#define STAGES 4
#define RC_OFF  (STAGES * STAGE_B)            // 61440
#define YSQ_OFF (RC_OFF + BM * 8 * 4)         // 63488
#define EB_OFF  (YSQ_OFF + BN * 4)            // 64000
#define SMEM_TOT (EB_OFF + BN * 4)            // 64512

__global__ __launch_bounds__(256, 3)
void hy_mma(int B, int N, int d) {
    extern __shared__ __align__(16) char smem[];
    const uint32_t sb = smem_u32(smem);

    const int tid = threadIdx.x;
    const int wid = tid >> 5;
    const int lane = tid & 31;
    const int m0 = blockIdx.y * BM;
    const int n0 = blockIdx.x * BN;
    const int NKT = d / BK;          // must be a multiple of 4 (d=512 -> 16)

    float* rc_s  = reinterpret_cast<float*>(smem + RC_OFF);
    float* ysq_s = reinterpret_cast<float*>(smem + YSQ_OFF);
    float* eb_s  = reinterpret_cast<float*>(smem + EB_OFF);

    // epilogue constants
    for (int idx = tid; idx < BM * 8; idx += 256) {
        int r = idx >> 3, cc = idx & 7, gm = m0 + r;
        rc_s[idx] = (gm < B) ? g_rowc[gm * 8 + cc] : 0.f;
    }
    for (int idx = tid; idx < BN; idx += 256) {
        int gn = n0 + idx;
        ysq_s[idx] = (gn < N) ? g_ysq[gn] : 0.f;
        eb_s[idx]  = (gn < N) ? g_eb[gn]  : 0.f;
    }

    // ---- loader: A 64 rows (1 chunk/thread), B 128 rows (2 chunks/thread) ----
    const int lrow = tid >> 2;          // 0..63
    const int lc16 = tid & 3;
    const int gmA0 = m0 + lrow;
    const bool okA0 = gmA0 < B;
    const int gnB0 = n0 + lrow,  gnB1 = n0 + lrow + 64;
    const bool okB0 = gnB0 < N,  okB1 = gnB1 < N;
    const __nv_bfloat16* pA0 = g_Qb + (long)(okA0 ? gmA0 : 0) * d + lc16 * 8;
    const __nv_bfloat16* pB0 = g_Cb + (long)(okB0 ? gnB0 : 0) * d + lc16 * 8;
    const __nv_bfloat16* pB1 = g_Cb + (long)(okB1 ? gnB1 : 0) * d + lc16 * 8;
    const uint32_t dA0 = sb + lrow * RSB + lc16 * 16;
    const uint32_t dB0 = sb + ATILE + lrow * RSB + lc16 * 16;
    const uint32_t dB1 = dB0 + 64 * RSB;

    // prologue: prefetch chunks 0..2 into stages 0..2
    #pragma unroll
    for (int s = 0; s < STAGES - 1; s++) {
        const uint32_t so = s * STAGE_B;
        cp16(dA0 + so, pA0, okA0);
        cp16(dB0 + so, pB0, okB0);  cp16(dB1 + so, pB1, okB1);
        CP_COMMIT();
        pA0 += BK; pB0 += BK; pB1 += BK;
    }
    // pointers now at chunk 3 == first in-loop prefetch target

    // warp tile: 32(m) x 32(n); 8 warps: 2(m) x 4(n)
    const int wm = (wid & 1) * 32;
    const int wn = (wid >> 1) * 32;
    const uint32_t a_base = sb + (wm + (lane & 15)) * RSB + (lane >> 4) * 16;
    const uint32_t b_base = sb + ATILE + (wn + (lane >> 4) * 8 + (lane & 7)) * RSB
                               + ((lane >> 3) & 1) * 16;

    float acc[2][4][4];
    #pragma unroll
    for (int mi = 0; mi < 2; mi++)
        #pragma unroll
        for (int ni = 0; ni < 4; ni++)
            #pragma unroll
            for (int q = 0; q < 4; q++) acc[mi][ni][q] = 0.f;

    // main loop: 4 chunks per outer iter; stage index == su (compile-time)
    for (int kt = 0; kt < NKT; kt += 4) {
        #pragma unroll
        for (int su = 0; su < 4; su++) {
            CP_WAIT(2);              // chunk kt+su complete (3-chunk slack)
            __syncthreads();

            // prefetch chunk kt+su+3 into stage (su+3)&3 (its readers finished at iter kt+su-1)
            if (kt + su + 3 < NKT) {
                const uint32_t so = ((su + 3) & 3) * STAGE_B;
                cp16(dA0 + so, pA0, okA0);
                cp16(dB0 + so, pB0, okB0);  cp16(dB1 + so, pB1, okB1);
                pA0 += BK; pB0 += BK; pB1 += BK;
            }
            CP_COMMIT();

            const uint32_t so = su * STAGE_B;   // compile-time constant offset
            #pragma unroll
            for (int ks = 0; ks < 2; ks++) {
                uint32_t a[2][4];
                #pragma unroll
                for (int mi = 0; mi < 2; mi++)
                    LDSM_X4(a[mi][0], a[mi][1], a[mi][2], a[mi][3],
                            a_base + so + mi * 16 * RSB + ks * 32);
                uint32_t b[2][4];
                #pragma unroll
                for (int g = 0; g < 2; g++)
                    LDSM_X4(b[g][0], b[g][1], b[g][2], b[g][3],
                            b_base + so + g * 16 * RSB + ks * 32);
                #pragma unroll
                for (int mi = 0; mi < 2; mi++)
                    #pragma unroll
                    for (int ni = 0; ni < 4; ni++)
                        MMA16816(acc[mi][ni], a[mi], b[ni >> 1][(ni & 1) * 2],
                                 b[ni >> 1][(ni & 1) * 2 + 1]);
            }
        }
    }

    // ---------------- epilogue ----------------
    #pragma unroll
    for (int mi = 0; mi < 2; mi++) {
        #pragma unroll
        for (int half = 0; half < 2; half++) {
            const int mrow = wm + mi * 16 + half * 8 + (lane >> 2);
            const int gm = m0 + mrow;
            const float* rc = rc_s + mrow * 8;
            const float c    = rc[0];
            const float xs   = rc[1];
            const float Bq   = rc[2];
            const float Bq2  = rc[3];
            const float c2xs = rc[4];
            const float sc   = rc[5];
            const float p    = rc[6];
            const float maxn = rc[7];
            const float m2c  = -2.f * c;
            const float m2Bq = -2.f * Bq;

            float rowsum = 0.f;
            #pragma unroll
            for (int ni = 0; ni < 4; ni++) {
                #pragma unroll
                for (int q = 0; q < 2; q++) {
                    float u  = acc[mi][ni][half * 2 + q];
                    int col  = wn + ni * 8 + 2 * (lane & 3) + q;
                    float v  = ysq_s[col];
                    float eb = eb_s[col];
                    float t    = fmaf(-2.f, u, v);
                    float A    = fmaf(c, t, 1.f);
                    float denp = fmaf(c2xs, v, fmaf(m2c, u, 1.f)) + EPS;
                    float ns   = fmaf(Bq2, v, A * fmaf(m2Bq, u, A * xs));
                    float r0   = sqrtf(fmaxf(ns, 0.f));
                    r0 = fminf(fmaxf(r0, EPS * denp), maxn * denp);
                    float s    = sc * r0;
                    float ratio = __fdividef(denp + s, denp - s);   // (1+z)/(1-z)
                    rowsum = fmaf(eb, fast_ex2(p * fast_lg2(ratio)), rowsum);
                }
            }
            rowsum += __shfl_xor_sync(0xffffffffu, rowsum, 1);
            rowsum += __shfl_xor_sync(0xffffffffu, rowsum, 2);
            if ((lane & 3) == 0 && gm < B) atomicAdd(&g_sumexp[gm], rowsum);
        }
    }
}

// ===================== finalize =====================
__global__ void hy_finalize(const float* __restrict__ Q, const float* __restrict__ C,
                            const float* __restrict__ bias, const int* __restrict__ tgt,
                            float* out, int B, int N, int d) {
    int w = (blockIdx.x * blockDim.x + threadIdx.x) >> 5;
    int lane = threadIdx.x & 31;
    if (w >= B) return;
    int t = tgt[w];
    const float* q  = Q + (long)w * d;
    const float* cd = C + (long)t * d;
    float s = 0.f;
    for (int k = lane * 4; k < d; k += 128) {
        float4 a = *reinterpret_cast<const float4*>(q + k);
        float4 b = *reinterpret_cast<const float4*>(cd + k);
        s += a.x*b.x + a.y*b.y + a.z*b.z + a.w*b.w;
    }
    #pragma unroll
    for (int o = 16; o > 0; o >>= 1) s += __shfl_xor_sync(0xffffffffu, s, o);
    if (lane == 0) {
        const float* rc = g_rowc + w * 8;
        float c = rc[0], xs = rc[1], Bq = rc[2], Bq2 = rc[3], c2xs = rc[4];
        float sc = rc[5], maxn = rc[7];
        float u = s, v = g_ysq[t];
        float tt  = fmaf(-2.f, u, v);
        float A   = fmaf(c, tt, 1.f);
        float den = fmaf(c2xs, v, fmaf(-2.f * c, u, 1.f));
        float ns  = fmaf(Bq2, v, A * fmaf(-2.f * Bq, u, A * xs));
        float r   = sqrtf(fmaxf(ns, 0.f));
        float dn  = r / (den + EPS);
        dn = fminf(fmaxf(dn, EPS), maxn);
        float z = fminf(sc * dn, 1.f - EPS);
        float dist = (2.f / (sc + EPS)) * atanhf(z);
        float tlogit = bias[t] - dist;
        float lse = logf(g_sumexp[w]);
        atomicAdd(out, (lse - tlogit) * (1.f / (float)B));
    }
}

// ===================== launch =====================
extern "C" void kernel_launch(void* const* d_in, const int* in_sizes, int n_in,
                              void* d_out, int out_size) {
    const float* Q    = (const float*)d_in[0];
    const float* C    = (const float*)d_in[1];
    const float* bias = (const float*)d_in[2];
    const float* curv = (const float*)d_in[3];
    const int*   tgt  = (const int*)d_in[4];
    float* out = (float*)d_out;

    int B = in_sizes[3];
    int N = in_sizes[2];
    int d = in_sizes[0] / B;

    hy_prep<<<((N + B) * 32 + 255) / 256, 256>>>(Q, C, bias, curv, out, B, N, d);

    cudaFuncSetAttribute(hy_mma, cudaFuncAttributeMaxDynamicSharedMemorySize, SMEM_TOT);
    dim3 grid((N + BN - 1) / BN, (B + BM - 1) / BM);
    hy_mma<<<grid, 256, SMEM_TOT>>>(B, N, d);

    hy_finalize<<<(B * 32 + 255) / 256, 256>>>(Q, C, bias, tgt, out, B, N, d);
}

// round 14
// speedup vs baseline: 1.6507x; 1.0193x over previous
#include <cuda_runtime.h>
#include <cuda_bf16.h>
#include <math.h>
#include <stdint.h>

#define EPS 1e-6f
#define MAXB 1024
#define MAXN 40000
#define MAXD 512

// ===================== fast math =====================
__device__ __forceinline__ float fast_lg2(float x) {
    float r; asm("lg2.approx.f32 %0, %1;" : "=f"(r) : "f"(x)); return r;
}
__device__ __forceinline__ float fast_ex2(float x) {
    float r; asm("ex2.approx.f32 %0, %1;" : "=f"(r) : "f"(x)); return r;
}
__device__ __forceinline__ float fast_sqrt(float x) {
    float r; asm("sqrt.approx.f32 %0, %1;" : "=f"(r) : "f"(x)); return r;
}
__device__ __forceinline__ uint32_t smem_u32(const void* p) {
    uint32_t a;
    asm("{ .reg .u64 t; cvta.to.shared.u64 t, %1; cvt.u32.u64 %0, t; }" : "=r"(a) : "l"(p));
    return a;
}

// ===================== mma.sync helpers =====================
#define LDSM_X4(r0, r1, r2, r3, addr)                                          \
    asm volatile("ldmatrix.sync.aligned.m8n8.x4.shared.b16 {%0,%1,%2,%3}, [%4];" \
        : "=r"(r0), "=r"(r1), "=r"(r2), "=r"(r3) : "r"(addr))

#define MMA16816(c, a, b0, b1)                                                 \
    asm volatile("mma.sync.aligned.m16n8k16.row.col.f32.bf16.bf16.f32 "        \
        "{%0,%1,%2,%3}, {%4,%5,%6,%7}, {%8,%9}, {%0,%1,%2,%3};"                \
        : "+f"((c)[0]), "+f"((c)[1]), "+f"((c)[2]), "+f"((c)[3])               \
        : "r"((a)[0]), "r"((a)[1]), "r"((a)[2]), "r"((a)[3]), "r"(b0), "r"(b1))

__device__ __forceinline__ void cp16(uint32_t dst, const void* src, bool pred) {
    int sz = pred ? 16 : 0;   // src-size 0 => zero-fill (keeps OOB tiles clean)
    asm volatile("cp.async.cg.shared.global [%0], [%1], 16, %2;"
        :: "r"(dst), "l"(src), "r"(sz) : "memory");
}
#define CP_COMMIT() asm volatile("cp.async.commit_group;" ::: "memory")
#define CP_WAIT(n)  asm volatile("cp.async.wait_group %0;" :: "n"(n) : "memory")

// ===================== scratch =====================
__device__ __align__(16) __nv_bfloat16 g_Qb[MAXB * MAXD];
__device__ __align__(16) __nv_bfloat16 g_Cb[MAXN * MAXD];
__device__ float g_ysq[MAXN];
__device__ float g_eb[MAXN];
__device__ float g_rowc[MAXB * 8];
__device__ float g_sumexp[MAXB];

// ===================== fused prep: init + candidates + queries =====================
__global__ void hy_prep(const float* __restrict__ Q, const float* __restrict__ C,
                        const float* __restrict__ bias, const float* __restrict__ curv,
                        float* out, int B, int N, int d) {
    const int gtid = blockIdx.x * blockDim.x + threadIdx.x;
    const int w = gtid >> 5;
    const int lane = gtid & 31;
    if (gtid < B) g_sumexp[gtid] = 0.f;
    if (gtid == 0) out[0] = 0.f;

    if (w < N) {
        const float* row = C + (long)w * d;
        __nv_bfloat16* brow = g_Cb + (long)w * d;
        float s = 0.f;
        for (int k = lane * 4; k < d; k += 128) {
            float4 v = *reinterpret_cast<const float4*>(row + k);
            s += v.x*v.x + v.y*v.y + v.z*v.z + v.w*v.w;
            __nv_bfloat162* bp = reinterpret_cast<__nv_bfloat162*>(brow + k);
            bp[0] = __floats2bfloat162_rn(v.x, v.y);
            bp[1] = __floats2bfloat162_rn(v.z, v.w);
        }
        #pragma unroll
        for (int o = 16; o > 0; o >>= 1) s += __shfl_xor_sync(0xffffffffu, s, o);
        if (lane == 0) { g_ysq[w] = s; g_eb[w] = expf(bias[w]); }
    } else if (w < N + B) {
        const int q = w - N;
        const float* row = Q + (long)q * d;
        __nv_bfloat16* brow = g_Qb + (long)q * d;
        float s = 0.f;
        for (int k = lane * 4; k < d; k += 128) {
            float4 v = *reinterpret_cast<const float4*>(row + k);
            s += v.x*v.x + v.y*v.y + v.z*v.z + v.w*v.w;
            __nv_bfloat162* bp = reinterpret_cast<__nv_bfloat162*>(brow + k);
            bp[0] = __floats2bfloat162_rn(v.x, v.y);
            bp[1] = __floats2bfloat162_rn(v.z, v.w);
        }
        #pragma unroll
        for (int o = 16; o > 0; o >>= 1) s += __shfl_xor_sync(0xffffffffu, s, o);
        if (lane == 0) {
            float c  = curv[q];
            float xs = s;
            float sc = sqrtf(c + EPS);
            float Bq = 1.f - c * xs;
            float* rc = g_rowc + q * 8;
            rc[0] = c;  rc[1] = xs;  rc[2] = Bq;  rc[3] = Bq * Bq;
            rc[4] = c * c * xs;  rc[5] = sc;
            rc[6] = -1.f / (sc + EPS);
            rc[7] = 1.f / (sc + EPS) - EPS;
        }
    }
}

// ===================== main HMMA fused kernel (persistent, never-draining pipeline) =====================
#define BM 64
#define BN 128
#define BK 32
#define RSB 80                      // padded row stride bytes (64B data + 16 pad)
#define ATILE (BM * RSB)            // 5120
#define BTILE (BN * RSB)            // 10240
#define STAGE_B (ATILE + BTILE)     // 15360
#define STAGES 4
#define RC_OFF  (STAGES * STAGE_B)            // 61440
#define YSQ_OFF (RC_OFF + BM * 8 * 4)         // 63488
#define EB_OFF  (YSQ_OFF + BN * 4)            // 64000
#define SMEM_TOT (EB_OFF + BN * 4)            // 64512

#define STAGE_CONSTS(MM0, NN0) do {                                            \
    for (int idx = tid; idx < BM * 8; idx += 256) {                            \
        int r = idx >> 3, cc = idx & 7, gm = (MM0) + r;                        \
        rc_s[idx] = (gm < B) ? g_rowc[gm * 8 + cc] : 0.f;                      \
    }                                                                          \
    for (int idx = tid; idx < BN; idx += 256) {                                \
        int gn = (NN0) + idx;                                                  \
        ysq_s[idx] = (gn < N) ? g_ysq[gn] : 0.f;                               \
        eb_s[idx]  = (gn < N) ? g_eb[gn]  : 0.f;                               \
    }                                                                          \
} while (0)

#define SET_PTRS(MM0, NN0) do {                                                \
    int _gmA0 = (MM0) + lrow;                                                  \
    int _gnB0 = (NN0) + lrow, _gnB1 = (NN0) + lrow + 64;                       \
    okA0 = _gmA0 < B;  okB0 = _gnB0 < N;  okB1 = _gnB1 < N;                    \
    pA0 = g_Qb + (long)(okA0 ? _gmA0 : 0) * d + lc16 * 8;                      \
    pB0 = g_Cb + (long)(okB0 ? _gnB0 : 0) * d + lc16 * 8;                      \
    pB1 = g_Cb + (long)(okB1 ? _gnB1 : 0) * d + lc16 * 8;                      \
} while (0)

#define PF(SO) do {                                                            \
    cp16(dA0 + (SO), pA0, okA0);                                               \
    cp16(dB0 + (SO), pB0, okB0);  cp16(dB1 + (SO), pB1, okB1);                 \
    pA0 += BK; pB0 += BK; pB1 += BK;                                           \
} while (0)

__global__ __launch_bounds__(256, 3)
void hy_mma(int B, int N, int d, int nblk_m, int nblk_n) {
    extern __shared__ __align__(16) char smem[];
    const uint32_t sb = smem_u32(smem);

    const int tid = threadIdx.x;
    const int wid = tid >> 5;
    const int lane = tid & 31;
    const int NKT = d / BK;            // 16 (multiple of 4 required)
    const int total = nblk_m * nblk_n;

    int blk = blockIdx.x;
    if (blk >= total) return;
    int n0 = (blk / nblk_m) * BN;
    int m0 = (blk % nblk_m) * BM;

    float* rc_s  = reinterpret_cast<float*>(smem + RC_OFF);
    float* ysq_s = reinterpret_cast<float*>(smem + YSQ_OFF);
    float* eb_s  = reinterpret_cast<float*>(smem + EB_OFF);

    // loader geometry
    const int lrow = tid >> 2;          // 0..63
    const int lc16 = tid & 3;
    const uint32_t dA0 = sb + lrow * RSB + lc16 * 16;
    const uint32_t dB0 = sb + ATILE + lrow * RSB + lc16 * 16;
    const uint32_t dB1 = dB0 + 64 * RSB;

    bool okA0, okB0, okB1;
    const __nv_bfloat16 *pA0, *pB0, *pB1;

    // warp tile: 32(m) x 32(n); 8 warps: 2(m) x 4(n)
    const int wm = (wid & 1) * 32;
    const int wn = (wid >> 1) * 32;
    const uint32_t a_base = sb + (wm + (lane & 15)) * RSB + (lane >> 4) * 16;
    const uint32_t b_base = sb + ATILE + (wn + (lane >> 4) * 8 + (lane & 7)) * RSB
                               + ((lane >> 3) & 1) * 16;

    // first block: stage constants + fill pipeline (chunks 0..2)
    STAGE_CONSTS(m0, n0);
    SET_PTRS(m0, n0);
    #pragma unroll
    for (int s = 0; s < STAGES - 1; s++) {
        PF(s * STAGE_B);
        CP_COMMIT();
    }
    __syncthreads();

    float acc[2][4][4];
    #pragma unroll
    for (int mi = 0; mi < 2; mi++)
        #pragma unroll
        for (int ni = 0; ni < 4; ni++)
            #pragma unroll
            for (int q = 0; q < 4; q++) acc[mi][ni][q] = 0.f;

    for (;;) {
        const int nextblk = blk + gridDim.x;
        const bool hasNext = nextblk < total;

        // ---- k mainloop: const-folded 4-stage, prefetch distance 3 ----
        for (int kt = 0; kt < NKT; kt += 4) {
            #pragma unroll
            for (int su = 0; su < 4; su++) {
                CP_WAIT(2);
                __syncthreads();

                // prefetch global chunk (kt+su+3): current block tail flows into next block head
                if (kt + su + 3 < NKT || hasNext) {
                    PF(((su + 3) & 3) * STAGE_B);
                }
                CP_COMMIT();

                // after the LAST current-block prefetch (fc = NKT-1 at kt=NKT-4, su=0),
                // repoint the loader at the next block's chunk 0
                if (su == 0) {
                    if (kt == NKT - 4 && hasNext) {
                        int nn0 = (nextblk / nblk_m) * BN;
                        int nm0 = (nextblk % nblk_m) * BM;
                        SET_PTRS(nm0, nn0);
                    }
                }

                const uint32_t so = su * STAGE_B;   // compile-time stage offset
                #pragma unroll
                for (int ks = 0; ks < 2; ks++) {
                    uint32_t a[2][4];
                    #pragma unroll
                    for (int mi = 0; mi < 2; mi++)
                        LDSM_X4(a[mi][0], a[mi][1], a[mi][2], a[mi][3],
                                a_base + so + mi * 16 * RSB + ks * 32);
                    uint32_t b[2][4];
                    #pragma unroll
                    for (int g = 0; g < 2; g++)
                        LDSM_X4(b[g][0], b[g][1], b[g][2], b[g][3],
                                b_base + so + g * 16 * RSB + ks * 32);
                    #pragma unroll
                    for (int mi = 0; mi < 2; mi++)
                        #pragma unroll
                        for (int ni = 0; ni < 4; ni++)
                            MMA16816(acc[mi][ni], a[mi], b[ni >> 1][(ni & 1) * 2],
                                     b[ni >> 1][(ni & 1) * 2 + 1]);
                }
            }
        }

        // ---- epilogue for current block ----
        #pragma unroll
        for (int mi = 0; mi < 2; mi++) {
            #pragma unroll
            for (int half = 0; half < 2; half++) {
                const int mrow = wm + mi * 16 + half * 8 + (lane >> 2);
                const int gm = m0 + mrow;
                const float* rc = rc_s + mrow * 8;
                const float c    = rc[0];
                const float xs   = rc[1];
                const float Bq   = rc[2];
                const float Bq2  = rc[3];
                const float c2xs = rc[4];
                const float sc   = rc[5];
                const float p    = rc[6];
                const float maxn = rc[7];
                const float m2c  = -2.f * c;
                const float m2Bq = -2.f * Bq;

                float rowsum = 0.f;
                #pragma unroll
                for (int ni = 0; ni < 4; ni++) {
                    #pragma unroll
                    for (int q = 0; q < 2; q++) {
                        float u  = acc[mi][ni][half * 2 + q];
                        int col  = wn + ni * 8 + 2 * (lane & 3) + q;
                        float v  = ysq_s[col];
                        float eb = eb_s[col];
                        float t    = fmaf(-2.f, u, v);
                        float A    = fmaf(c, t, 1.f);
                        float denp = fmaf(c2xs, v, fmaf(m2c, u, 1.f)) + EPS;
                        float ns   = fmaf(Bq2, v, A * fmaf(m2Bq, u, A * xs));
                        float r0   = fast_sqrt(fmaxf(ns, 0.f));
                        r0 = fminf(fmaxf(r0, EPS * denp), maxn * denp);
                        float s    = sc * r0;
                        float ratio = __fdividef(denp + s, denp - s);   // (1+z)/(1-z)
                        rowsum = fmaf(eb, fast_ex2(p * fast_lg2(ratio)), rowsum);
                    }
                }
                rowsum += __shfl_xor_sync(0xffffffffu, rowsum, 1);
                rowsum += __shfl_xor_sync(0xffffffffu, rowsum, 2);
                if ((lane & 3) == 0 && gm < B) atomicAdd(&g_sumexp[gm], rowsum);
            }
        }

        if (!hasNext) break;

        // advance to next block: restage constants (chunk prefetches already in flight)
        blk = nextblk;
        n0 = (blk / nblk_m) * BN;
        m0 = (blk % nblk_m) * BM;
        __syncthreads();                 // all warps done reading current consts
        STAGE_CONSTS(m0, n0);
        // (k-loop's first CP_WAIT+__syncthreads makes these stores visible)

        #pragma unroll
        for (int mi = 0; mi < 2; mi++)
            #pragma unroll
            for (int ni = 0; ni < 4; ni++)
                #pragma unroll
                for (int q = 0; q < 4; q++) acc[mi][ni][q] = 0.f;
    }
}

// ===================== finalize =====================
__global__ void hy_finalize(const float* __restrict__ Q, const float* __restrict__ C,
                            const float* __restrict__ bias, const int* __restrict__ tgt,
                            float* out, int B, int N, int d) {
    int w = (blockIdx.x * blockDim.x + threadIdx.x) >> 5;
    int lane = threadIdx.x & 31;
    if (w >= B) return;
    int t = tgt[w];
    const float* q  = Q + (long)w * d;
    const float* cd = C + (long)t * d;
    float s = 0.f;
    for (int k = lane * 4; k < d; k += 128) {
        float4 a = *reinterpret_cast<const float4*>(q + k);
        float4 b = *reinterpret_cast<const float4*>(cd + k);
        s += a.x*b.x + a.y*b.y + a.z*b.z + a.w*b.w;
    }
    #pragma unroll
    for (int o = 16; o > 0; o >>= 1) s += __shfl_xor_sync(0xffffffffu, s, o);
    if (lane == 0) {
        const float* rc = g_rowc + w * 8;
        float c = rc[0], xs = rc[1], Bq = rc[2], Bq2 = rc[3], c2xs = rc[4];
        float sc = rc[5], maxn = rc[7];
        float u = s, v = g_ysq[t];
        float tt  = fmaf(-2.f, u, v);
        float A   = fmaf(c, tt, 1.f);
        float den = fmaf(c2xs, v, fmaf(-2.f * c, u, 1.f));
        float ns  = fmaf(Bq2, v, A * fmaf(-2.f * Bq, u, A * xs));
        float r   = sqrtf(fmaxf(ns, 0.f));
        float dn  = r / (den + EPS);
        dn = fminf(fmaxf(dn, EPS), maxn);
        float z = fminf(sc * dn, 1.f - EPS);
        float dist = (2.f / (sc + EPS)) * atanhf(z);
        float tlogit = bias[t] - dist;
        float lse = logf(g_sumexp[w]);
        atomicAdd(out, (lse - tlogit) * (1.f / (float)B));
    }
}

// ===================== launch =====================
extern "C" void kernel_launch(void* const* d_in, const int* in_sizes, int n_in,
                              void* d_out, int out_size) {
    const float* Q    = (const float*)d_in[0];
    const float* C    = (const float*)d_in[1];
    const float* bias = (const float*)d_in[2];
    const float* curv = (const float*)d_in[3];
    const int*   tgt  = (const int*)d_in[4];
    float* out = (float*)d_out;

    int B = in_sizes[3];
    int N = in_sizes[2];
    int d = in_sizes[0] / B;

    hy_prep<<<((N + B) * 32 + 255) / 256, 256>>>(Q, C, bias, curv, out, B, N, d);

    static int nsm = -1;
    if (nsm < 0) {
        cudaDeviceGetAttribute(&nsm, cudaDevAttrMultiProcessorCount, 0);
        cudaFuncSetAttribute(hy_mma, cudaFuncAttributeMaxDynamicSharedMemorySize, SMEM_TOT);
    }
    int nblk_m = (B + BM - 1) / BM;          // 16
    int nblk_n = (N + BN - 1) / BN;          // 313
    int total = nblk_m * nblk_n;
    int grid = nsm * 3 < total ? nsm * 3 : total;
    hy_mma<<<grid, 256, SMEM_TOT>>>(B, N, d, nblk_m, nblk_n);

    hy_finalize<<<(B * 32 + 255) / 256, 256>>>(Q, C, bias, tgt, out, B, N, d);
}